// round 7
// baseline (speedup 1.0000x reference)
#include <cuda_runtime.h>
#include <math.h>
#include <stdint.h>

#define BB   4
#define SS   1024
#define DD   768
#define HH   12
#define VV   32000
#define LL   2
#define DK   64
#define DFF  3072
#define MM   (BB*SS)
#define QSTR (3*DD)

#define LOGITS_ELEMS ((size_t)BB*SS*VV)
#define AMAP_ELEMS   ((size_t)BB*HH*SS*SS)

// ---------------- scratch ----------------
__device__ float g_h  [MM*DD];     // fp32 residual stream
__device__ float g_ht [MM*DD];     // tf32-rounded copy of h
__device__ float g_qkv[MM*QSTR];   // rounded qkv
__device__ float g_ot [MM*DD];     // rounded attention output
__device__ float g_p  [MM*DD];     // fp32 proj / ff2 output
__device__ float g_fft[MM*DFF];    // rounded relu(ff1)
__device__ float g_wt [(size_t)DD*VV]; // rounded weight, k-major [K][N]
__device__ float g_b3 [QSTR];

__device__ __forceinline__ uint32_t f2tf32(float x) {
    uint32_t r;
    asm("cvt.rna.tf32.f32 %0, %1;" : "=r"(r) : "f"(x));
    return r;
}
__device__ __forceinline__ float tf32r(float x) {
    return __uint_as_float(f2tf32(x));
}
__device__ __forceinline__ void cp_async16(void* sdst, const void* gsrc) {
    uint32_t s = (uint32_t)__cvta_generic_to_shared(sdst);
    asm volatile("cp.async.cg.shared.global [%0], [%1], 16;" :: "r"(s), "l"(gsrc));
}
#define CP_COMMIT() asm volatile("cp.async.commit_group;")
#define CP_WAIT(n)  asm volatile("cp.async.wait_group %0;" :: "n"(n))

#define LDSM4(R0,R1,R2,R3,ADDR) \
    asm volatile("ldmatrix.sync.aligned.m8n8.x4.shared.b16 {%0,%1,%2,%3}, [%4];" \
        : "=r"(R0), "=r"(R1), "=r"(R2), "=r"(R3) : "r"(ADDR))

#define MMA_TF32(ACC, AF, B0, B1) \
    asm volatile("mma.sync.aligned.m16n8k8.row.col.f32.tf32.tf32.f32 " \
        "{%0,%1,%2,%3}, {%4,%5,%6,%7}, {%8,%9}, {%0,%1,%2,%3};" \
        : "+f"((ACC)[0]), "+f"((ACC)[1]), "+f"((ACC)[2]), "+f"((ACC)[3]) \
        : "r"((AF)[0]), "r"((AF)[1]), "r"((AF)[2]), "r"((AF)[3]), \
          "r"(B0), "r"(B1))

// ---------------- weight rounding (linear, k-major preserved) -------------
__global__ void cvt_tf32_kernel(const float4* __restrict__ src,
                                float4* __restrict__ dst, int n4)
{
    int i = blockIdx.x * 256 + threadIdx.x;
    if (i >= n4) return;
    float4 v = src[i];
    v.x = tf32r(v.x); v.y = tf32r(v.y); v.z = tf32r(v.z); v.w = tf32r(v.w);
    dst[i] = v;
}
// round + pack into [K][2304] column block
__global__ void cvt_tf32_cols_kernel(const float* __restrict__ src,
                                     float* __restrict__ dst,
                                     int rows, int cols, int dstr, int coff)
{
    int i = blockIdx.x * 256 + threadIdx.x;
    int c4 = cols >> 2;
    if (i >= rows * c4) return;
    int r = i / c4;
    int c = (i - r*c4) << 2;
    float4 v = *(const float4*)(src + (size_t)r*cols + c);
    v.x = tf32r(v.x); v.y = tf32r(v.y); v.z = tf32r(v.z); v.w = tf32r(v.w);
    *(float4*)(dst + (size_t)r*dstr + coff + c) = v;
}
__global__ void concat3_kernel(const float* __restrict__ a,
                               const float* __restrict__ b,
                               const float* __restrict__ c,
                               float* __restrict__ dst)
{
    int i = blockIdx.x * 256 + threadIdx.x;
    if (i >= QSTR) return;
    dst[i] = (i < DD) ? a[i] : (i < 2*DD ? b[i-DD] : c[i-2*DD]);
}

// ---------------- embedding (fp32 + rounded) -------------------------------
__global__ void embed_kernel(const int* __restrict__ x,
                             const float* __restrict__ emb,
                             const float* __restrict__ pe)
{
    int i = blockIdx.x * 256 + threadIdx.x;
    if (i >= MM*DD) return;
    int row = i / DD;
    int d   = i - row*DD;
    int s   = row & (SS-1);
    int tok = x[row];
    float v = emb[(size_t)tok*DD + d] * 27.712812921102035f + pe[(size_t)s*DD + d];
    g_h[i]  = v;
    g_ht[i] = tf32r(v);
}

// ============ TF32 GEMM: A ldmatrix, B scalar LDS, pre-rounded operands ===
// C[M,N] = A[M,K] @ W[K,N] + bias. BM=BN=128, BK=32, 2-stage, 2 CTAs/SM.
// mode: bit0 = relu, bit1 = round output to tf32.
#define A_STR 36
#define B_STR 136
#define A_TILE_F (128*A_STR)
#define B_TILE_F (32*B_STR)
#define GEMM_SMEM (2*(A_TILE_F + B_TILE_F)*4)

__global__ __launch_bounds__(256, 2)
void gemm_tf32_kernel(const float* __restrict__ A,
                      const float* __restrict__ W,
                      const float* __restrict__ bias,
                      float* __restrict__ C,
                      int K, int N, int mode)
{
    extern __shared__ float smem[];
    float* As = smem;
    float* Bs = smem + 2*A_TILE_F;

    const int tid    = threadIdx.x;
    const int wid    = tid >> 5;
    const int lane   = tid & 31;
    const int gr     = lane >> 2;
    const int ctg    = lane & 3;
    const int warp_m = wid >> 2;   // 0..1 -> 64 rows
    const int warp_n = wid & 3;    // 0..3 -> 32 cols

    const int row0 = blockIdx.x * 128;
    const int col0 = blockIdx.y * 128;

    const int a_m  = tid >> 1;
    const int a_kq = (tid & 1) * 16;
    const int b_k  = tid >> 3;
    const int b_nq = (tid & 7) * 16;

    const float* a_src = A + (size_t)(row0 + a_m)*K + a_kq;
    const float* b_src = W + (size_t)b_k*N + col0 + b_nq;

    const int row_a = ((lane >> 3) & 1) * 8 + (lane & 7);
    const int col_a = (lane >> 4) * 4;

    const uint32_t as_base = (uint32_t)__cvta_generic_to_shared(As);

    float acc[4][4][4] = {};
    const int ntiles = K >> 5;

#define G_ISSUE(tile, slot) do { \
    float* ad = &As[(slot)*A_TILE_F + a_m*A_STR + a_kq]; \
    const float* ag = a_src + (tile)*32; \
    cp_async16(ad,    ag);    cp_async16(ad+4,  ag+4); \
    cp_async16(ad+8,  ag+8);  cp_async16(ad+12, ag+12); \
    float* bd = &Bs[(slot)*B_TILE_F + b_k*B_STR + b_nq]; \
    const float* bg = b_src + (size_t)(tile)*32*N; \
    cp_async16(bd,    bg);    cp_async16(bd+4,  bg+4); \
    cp_async16(bd+8,  bg+8);  cp_async16(bd+12, bg+12); \
} while (0)

    G_ISSUE(0, 0); CP_COMMIT();

    for (int t = 0; t < ntiles; t++) {
        const int cur = t & 1;
        if (t + 1 < ntiles) {
            G_ISSUE(t + 1, cur ^ 1);
            CP_COMMIT();
            CP_WAIT(1);
        } else {
            CP_WAIT(0);
        }
        __syncthreads();

        #pragma unroll
        for (int kk = 0; kk < 32; kk += 8) {
            uint32_t af[4][4];
            #pragma unroll
            for (int mt = 0; mt < 4; mt++) {
                uint32_t addr = as_base + 4u*((uint32_t)(cur*A_TILE_F)
                              + (uint32_t)((warp_m*64 + mt*16 + row_a)*A_STR)
                              + (uint32_t)(col_a + kk));
                LDSM4(af[mt][0], af[mt][1], af[mt][2], af[mt][3], addr);
            }
            uint32_t bf[4][2];
            #pragma unroll
            for (int nt = 0; nt < 4; nt++) {
                const float* bp = &Bs[cur*B_TILE_F + (kk+ctg)*B_STR + warp_n*32 + nt*8 + gr];
                bf[nt][0] = __float_as_uint(bp[0]);
                bf[nt][1] = __float_as_uint(bp[4*B_STR]);
            }
            #pragma unroll
            for (int mt = 0; mt < 4; mt++)
                #pragma unroll
                for (int nt = 0; nt < 4; nt++)
                    MMA_TF32(acc[mt][nt], af[mt], bf[nt][0], bf[nt][1]);
        }
        __syncthreads();
    }
#undef G_ISSUE

    #pragma unroll
    for (int mt = 0; mt < 4; mt++) {
        int r_base = row0 + warp_m*64 + mt*16 + gr;
        #pragma unroll
        for (int nt = 0; nt < 4; nt++) {
            int c_base = col0 + warp_n*32 + nt*8 + 2*ctg;
            float b0 = bias[c_base], b1 = bias[c_base+1];
            float v0 = acc[mt][nt][0] + b0;
            float v1 = acc[mt][nt][1] + b1;
            float v2 = acc[mt][nt][2] + b0;
            float v3 = acc[mt][nt][3] + b1;
            if (mode & 1) {
                v0 = fmaxf(v0, 0.f); v1 = fmaxf(v1, 0.f);
                v2 = fmaxf(v2, 0.f); v3 = fmaxf(v3, 0.f);
            }
            if (mode & 2) {
                v0 = tf32r(v0); v1 = tf32r(v1);
                v2 = tf32r(v2); v3 = tf32r(v3);
            }
            *(float2*)(C + (size_t)r_base*N + c_base)     = make_float2(v0, v1);
            *(float2*)(C + (size_t)(r_base+8)*N + c_base) = make_float2(v2, v3);
        }
    }
}

// ============ attention scores: S = Q @ K^T (operands pre-rounded) ========
#define S_STR 68
#define SCORES_SMEM (2*128*S_STR*4)

__global__ __launch_bounds__(256)
void attn_scores_gemm(const float* __restrict__ qkv,
                      float* __restrict__ amap)
{
    extern __shared__ float smem[];
    float* As = smem;
    float* Bs = smem + 128*S_STR;

    const int tid    = threadIdx.x;
    const int wid    = tid >> 5;
    const int lane   = tid & 31;
    const int gr     = lane >> 2;
    const int ctg    = lane & 3;
    const int warp_m = wid >> 2;
    const int warp_n = wid & 3;

    int idx = blockIdx.x;
    int qb = 0;
    while ((qb+1)*(qb+2)/2 <= idx) qb++;
    int kb = idx - qb*(qb+1)/2;

    const int bh = blockIdx.y;
    const int b  = bh / HH;
    const int hh = bh - b*HH;

    const int row0 = qb * 128;
    const int col0 = kb * 128;

    const float* Qb = qkv + (size_t)(b*SS)*QSTR + hh*DK;
    const float* Kb = Qb + DD;

    const int l_m  = tid >> 1;
    const int l_kq = (tid & 1) * 32;

    {
        const float* ag = Qb + (size_t)(row0 + l_m)*QSTR + l_kq;
        float* ad = &As[l_m*S_STR + l_kq];
        #pragma unroll
        for (int i = 0; i < 8; i++) cp_async16(ad + 4*i, ag + 4*i);
        const float* bg = Kb + (size_t)(col0 + l_m)*QSTR + l_kq;
        float* bd = &Bs[l_m*S_STR + l_kq];
        #pragma unroll
        for (int i = 0; i < 8; i++) cp_async16(bd + 4*i, bg + 4*i);
    }
    CP_COMMIT();
    CP_WAIT(0);
    __syncthreads();

    const int row_a = ((lane >> 3) & 1) * 8 + (lane & 7);
    const int col_a = (lane >> 4) * 4;
    const uint32_t as_base = (uint32_t)__cvta_generic_to_shared(As);
    const uint32_t bs_base = (uint32_t)__cvta_generic_to_shared(Bs);

    float acc[4][4][4] = {};

    #pragma unroll
    for (int kk = 0; kk < 64; kk += 8) {
        uint32_t af[4][4];
        #pragma unroll
        for (int mt = 0; mt < 4; mt++) {
            uint32_t addr = as_base + 4u*(uint32_t)((warp_m*64 + mt*16 + row_a)*S_STR + col_a + kk);
            LDSM4(af[mt][0], af[mt][1], af[mt][2], af[mt][3], addr);
        }
        uint32_t bf[4][2];
        #pragma unroll
        for (int p = 0; p < 2; p++) {
            uint32_t addr = bs_base + 4u*(uint32_t)((warp_n*32 + p*16 + row_a)*S_STR + col_a + kk);
            uint32_t r0, r1, r2, r3;
            LDSM4(r0, r1, r2, r3, addr);
            bf[2*p  ][0] = r0;
            bf[2*p+1][0] = r1;
            bf[2*p  ][1] = r2;
            bf[2*p+1][1] = r3;
        }
        #pragma unroll
        for (int mt = 0; mt < 4; mt++)
            #pragma unroll
            for (int nt = 0; nt < 4; nt++)
                MMA_TF32(acc[mt][nt], af[mt], bf[nt][0], bf[nt][1]);
    }

    float* Sb = amap + (size_t)bh*SS*SS;
    #pragma unroll
    for (int mt = 0; mt < 4; mt++) {
        int r = row0 + warp_m*64 + mt*16 + gr;
        #pragma unroll
        for (int nt = 0; nt < 4; nt++) {
            int c = col0 + warp_n*32 + nt*8 + 2*ctg;
            *(float2*)(Sb + (size_t)r*SS + c) =
                make_float2(acc[mt][nt][0]*0.125f, acc[mt][nt][1]*0.125f);
            *(float2*)(Sb + (size_t)(r+8)*SS + c) =
                make_float2(acc[mt][nt][2]*0.125f, acc[mt][nt][3]*0.125f);
        }
    }
}

// ============ softmax rows, in place ======================================
__global__ void softmax_rows(float* __restrict__ amap)
{
    const int qpos = blockIdx.x;
    const int bh   = blockIdx.y;
    const int tid  = threadIdx.x;
    const int wid  = tid >> 5;
    const int lane = tid & 31;

    float* row = amap + ((size_t)bh*SS + qpos)*SS;

    __shared__ float sc[SS];
    __shared__ float red[8];
    __shared__ float bcast;

    float m = -1e30f;
    for (int k = tid; k <= qpos; k += 256) {
        float v = row[k];
        sc[k] = v;
        m = fmaxf(m, v);
    }
    #pragma unroll
    for (int o = 16; o > 0; o >>= 1) m = fmaxf(m, __shfl_xor_sync(0xffffffffu, m, o));
    if (lane == 0) red[wid] = m;
    __syncthreads();
    if (tid == 0) {
        float mm = red[0];
        #pragma unroll
        for (int i = 1; i < 8; i++) mm = fmaxf(mm, red[i]);
        bcast = mm;
    }
    __syncthreads();
    m = bcast;

    float s = 0.0f;
    for (int k = tid; k <= qpos; k += 256) {
        float e = __expf(sc[k] - m);
        sc[k] = e;
        s += e;
    }
    #pragma unroll
    for (int o = 16; o > 0; o >>= 1) s += __shfl_xor_sync(0xffffffffu, s, o);
    if (lane == 0) red[wid] = s;
    __syncthreads();
    if (tid == 0) {
        float ss = red[0];
        #pragma unroll
        for (int i = 1; i < 8; i++) ss += red[i];
        bcast = 1.0f / ss;
    }
    __syncthreads();
    float inv = bcast;

    for (int k = tid; k < SS; k += 256)
        row[k] = (k <= qpos) ? sc[k] * inv : 0.0f;
}

// ============ attn_o: O = amap @ V, rounded output ========================
#define AS_PAD 36
#define BO_PAD 68
#define ATTN_SMEM ((2*128*AS_PAD + 2*32*BO_PAD)*4)
__global__ __launch_bounds__(256)
void attn_o_mma_kernel(const float* __restrict__ amap,
                       const float* __restrict__ qkv,
                       float* __restrict__ O)
{
    extern __shared__ float smem[];
    float* As = smem;
    float* Bs = smem + 2*128*AS_PAD;
#define ASM(b,m,k) As[((b)*128+(m))*AS_PAD+(k)]
#define BSM(b,k,n) Bs[((b)*32+(k))*BO_PAD+(n)]

    const int tid    = threadIdx.x;
    const int wid    = tid >> 5;
    const int lane   = tid & 31;
    const int gr     = lane >> 2;
    const int ctg    = lane & 3;
    const int warp_m = wid & 3;
    const int warp_n = wid >> 2;

    const int row0 = blockIdx.x * 128;
    const int bh   = blockIdx.y;
    const int b    = bh / HH;
    const int hh   = bh - b*HH;

    const float* Arow = amap + (size_t)bh*SS*SS;
    const float* Vb   = qkv + (size_t)(b*SS)*QSTR + 2*DD + hh*DK;

    const int a_m  = tid >> 1;
    const int a_kq = (tid & 1) * 16;
    const int b_k  = tid >> 3;
    const int b_nq = (tid & 7) * 8;

    const float* a_src = Arow + (size_t)(row0 + a_m)*SS + a_kq;
    const float* b_src = Vb + (size_t)b_k*QSTR + b_nq;

    float acc[2][4][4] = {};
    const int nt = (row0 + 128) >> 5;

    #pragma unroll
    for (int i = 0; i < 4; i++) cp_async16(&ASM(0, a_m, a_kq + 4*i), a_src + 4*i);
    #pragma unroll
    for (int i = 0; i < 2; i++) cp_async16(&BSM(0, b_k, b_nq + 4*i), b_src + 4*i);
    CP_COMMIT();

    for (int t = 0; t < nt; t++) {
        const int cur = t & 1;
        if (t + 1 < nt) {
            const int nb = cur ^ 1;
            const int k0 = (t+1) << 5;
            #pragma unroll
            for (int i = 0; i < 4; i++)
                cp_async16(&ASM(nb, a_m, a_kq + 4*i), a_src + k0 + 4*i);
            #pragma unroll
            for (int i = 0; i < 2; i++)
                cp_async16(&BSM(nb, b_k, b_nq + 4*i), b_src + (size_t)k0*QSTR + 4*i);
            CP_COMMIT();
            CP_WAIT(1);
        } else {
            CP_WAIT(0);
        }
        __syncthreads();

        #pragma unroll
        for (int kk = 0; kk < 32; kk += 8) {
            uint32_t af[2][4];
            #pragma unroll
            for (int mt = 0; mt < 2; mt++) {
                int mb = warp_m*32 + mt*16;
                af[mt][0] = f2tf32(ASM(cur, mb+gr,   kk+ctg));
                af[mt][1] = f2tf32(ASM(cur, mb+gr+8, kk+ctg));
                af[mt][2] = f2tf32(ASM(cur, mb+gr,   kk+ctg+4));
                af[mt][3] = f2tf32(ASM(cur, mb+gr+8, kk+ctg+4));
            }
            uint32_t bf[4][2];
            #pragma unroll
            for (int ntl = 0; ntl < 4; ntl++) {
                int nb = warp_n*32 + ntl*8;
                bf[ntl][0] = __float_as_uint(BSM(cur, kk+ctg,   nb+gr));
                bf[ntl][1] = __float_as_uint(BSM(cur, kk+ctg+4, nb+gr));
            }
            #pragma unroll
            for (int mt = 0; mt < 2; mt++)
                #pragma unroll
                for (int ntl = 0; ntl < 4; ntl++)
                    MMA_TF32(acc[mt][ntl], af[mt], bf[ntl][0], bf[ntl][1]);
        }
        __syncthreads();
    }

    #pragma unroll
    for (int mt = 0; mt < 2; mt++) {
        int r = row0 + warp_m*32 + mt*16 + gr;
        #pragma unroll
        for (int ntl = 0; ntl < 4; ntl++) {
            int c = warp_n*32 + ntl*8 + 2*ctg;
            float* dst = O + (size_t)(b*SS + r)*DD + hh*DK + c;
            *(float2*)dst = make_float2(tf32r(acc[mt][ntl][0]), tf32r(acc[mt][ntl][1]));
            *(float2*)(dst + 8*DD) = make_float2(tf32r(acc[mt][ntl][2]), tf32r(acc[mt][ntl][3]));
        }
    }
#undef ASM
#undef BSM
}

// ---------------- residual add + layernorm (fp32 + rounded outputs) -------
__global__ void add_ln_kernel(const float* __restrict__ res,
                              const float* __restrict__ x,
                              const float* __restrict__ g,
                              const float* __restrict__ be,
                              float* __restrict__ out,
                              float* __restrict__ outt)
{
    const int row = blockIdx.x;
    const int tid = threadIdx.x;
    __shared__ float buf[DD];
    __shared__ float red[256];

    float s = 0.0f;
    for (int d = tid; d < DD; d += 256) {
        float v = res[(size_t)row*DD + d] + x[(size_t)row*DD + d];
        buf[d] = v;
        s += v;
    }
    red[tid] = s; __syncthreads();
    for (int t = 128; t > 0; t >>= 1) {
        if (tid < t) red[tid] += red[tid+t];
        __syncthreads();
    }
    float mean = red[0] * (1.0f/DD);
    __syncthreads();

    float vs = 0.0f;
    for (int d = tid; d < DD; d += 256) {
        float dv = buf[d] - mean;
        vs += dv*dv;
    }
    red[tid] = vs; __syncthreads();
    for (int t = 128; t > 0; t >>= 1) {
        if (tid < t) red[tid] += red[tid+t];
        __syncthreads();
    }
    float rstd = rsqrtf(red[0] * (1.0f/DD) + 1e-5f);

    for (int d = tid; d < DD; d += 256) {
        float v = (buf[d] - mean)*rstd*g[d] + be[d];
        out [(size_t)row*DD + d] = v;
        outt[(size_t)row*DD + d] = tf32r(v);
    }
}

// ---------------------------------------------------------------------------
static inline void cvtw(const float* src, float* dst, size_t n) {
    int n4 = (int)(n >> 2);
    cvt_tf32_kernel<<<(n4 + 255)/256, 256>>>((const float4*)src, (float4*)dst, n4);
}

extern "C" void kernel_launch(void* const* d_in, const int* in_sizes, int n_in,
                              void* d_out, int out_size)
{
    (void)in_sizes; (void)n_in; (void)out_size;

    const int*   x    = (const int*)  d_in[0];
    const float* emb  = (const float*)d_in[2];
    const float* pe   = (const float*)d_in[3];
    const float* wq   = (const float*)d_in[4];
    const float* bq   = (const float*)d_in[5];
    const float* wk   = (const float*)d_in[6];
    const float* bk   = (const float*)d_in[7];
    const float* wv   = (const float*)d_in[8];
    const float* bv   = (const float*)d_in[9];
    const float* wo   = (const float*)d_in[10];
    const float* bo   = (const float*)d_in[11];
    const float* w1   = (const float*)d_in[12];
    const float* b1   = (const float*)d_in[13];
    const float* w2   = (const float*)d_in[14];
    const float* b2   = (const float*)d_in[15];
    const float* g1   = (const float*)d_in[16];
    const float* be1  = (const float*)d_in[17];
    const float* g2   = (const float*)d_in[18];
    const float* be2  = (const float*)d_in[19];
    const float* wout = (const float*)d_in[20];
    const float* bout = (const float*)d_in[21];
    float* out = (float*)d_out;

    static float *p_h=nullptr,*p_ht,*p_qkv,*p_ot,*p_p,*p_fft,*p_wt,*p_b3;
    if (!p_h) {
        void* p;
        cudaGetSymbolAddress(&p, g_h);   p_h   = (float*)p;
        cudaGetSymbolAddress(&p, g_ht);  p_ht  = (float*)p;
        cudaGetSymbolAddress(&p, g_qkv); p_qkv = (float*)p;
        cudaGetSymbolAddress(&p, g_ot);  p_ot  = (float*)p;
        cudaGetSymbolAddress(&p, g_p);   p_p   = (float*)p;
        cudaGetSymbolAddress(&p, g_fft); p_fft = (float*)p;
        cudaGetSymbolAddress(&p, g_wt);  p_wt  = (float*)p;
        cudaGetSymbolAddress(&p, g_b3);  p_b3  = (float*)p;
        cudaFuncSetAttribute(gemm_tf32_kernel,
            cudaFuncAttributeMaxDynamicSharedMemorySize, GEMM_SMEM);
        cudaFuncSetAttribute(attn_scores_gemm,
            cudaFuncAttributeMaxDynamicSharedMemorySize, SCORES_SMEM);
        cudaFuncSetAttribute(attn_o_mma_kernel,
            cudaFuncAttributeMaxDynamicSharedMemorySize, ATTN_SMEM);
    }

    embed_kernel<<<(MM*DD + 255)/256, 256>>>(x, emb, pe);

    const int wblk = (DD*DD/4 + 255)/256;

    for (int l = 0; l < LL; l++) {
        const float* wq_l = wq + (size_t)l*DD*DD;
        const float* wk_l = wk + (size_t)l*DD*DD;
        const float* wv_l = wv + (size_t)l*DD*DD;
        const float* wo_l = wo + (size_t)l*DD*DD;
        const float* w1_l = w1 + (size_t)l*DD*DFF;
        const float* w2_l = w2 + (size_t)l*DFF*DD;

        // ---- fused QKV ----
        cvt_tf32_cols_kernel<<<wblk, 256>>>(wq_l, p_wt, DD, DD, QSTR, 0);
        cvt_tf32_cols_kernel<<<wblk, 256>>>(wk_l, p_wt, DD, DD, QSTR, DD);
        cvt_tf32_cols_kernel<<<wblk, 256>>>(wv_l, p_wt, DD, DD, QSTR, 2*DD);
        concat3_kernel<<<(QSTR+255)/256, 256>>>(bq + l*DD, bk + l*DD, bv + l*DD, p_b3);
        dim3 gqkv(MM/128, QSTR/128);
        gemm_tf32_kernel<<<gqkv, 256, GEMM_SMEM>>>(p_ht, p_wt, p_b3, p_qkv, DD, QSTR, 2);

        // ---- attention ----
        float* amap_l = out + LOGITS_ELEMS + (size_t)l*AMAP_ELEMS;
        dim3 gsc(36, BB*HH);
        attn_scores_gemm<<<gsc, 256, SCORES_SMEM>>>(p_qkv, amap_l);
        dim3 gsm(SS, BB*HH);
        softmax_rows<<<gsm, 256>>>(amap_l);
        dim3 gao(SS/128, BB*HH);
        attn_o_mma_kernel<<<gao, 256, ATTN_SMEM>>>(amap_l, p_qkv, p_ot);

        // ---- output projection ----
        cvtw(wo_l, p_wt, (size_t)DD*DD);
        dim3 gproj(MM/128, DD/128);
        gemm_tf32_kernel<<<gproj, 256, GEMM_SMEM>>>(p_ot, p_wt, bo + l*DD, p_p, DD, DD, 0);
        add_ln_kernel<<<MM, 256>>>(p_h, p_p, g1 + l*DD, be1 + l*DD, p_h, p_ht);

        // ---- FFN ----
        cvtw(w1_l, p_wt, (size_t)DD*DFF);
        dim3 gff1(MM/128, DFF/128);
        gemm_tf32_kernel<<<gff1, 256, GEMM_SMEM>>>(p_ht, p_wt, b1 + l*DFF, p_fft, DD, DFF, 3);

        cvtw(w2_l, p_wt, (size_t)DFF*DD);
        dim3 gff2(MM/128, DD/128);
        gemm_tf32_kernel<<<gff2, 256, GEMM_SMEM>>>(p_fft, p_wt, b2 + l*DD, p_p, DFF, DD, 0);
        add_ln_kernel<<<MM, 256>>>(p_h, p_p, g2 + l*DD, be2 + l*DD, p_h, p_ht);
    }

    // ---- logits ----
    cvtw(wout, p_wt, (size_t)DD*VV);
    dim3 glog(MM/128, VV/128);
    gemm_tf32_kernel<<<glog, 256, GEMM_SMEM>>>(p_ht, p_wt, bout, out, DD, VV, 0);
}

// round 8
// speedup vs baseline: 1.4628x; 1.4628x over previous
#include <cuda_runtime.h>
#include <math.h>
#include <stdint.h>

#define BB   4
#define SS   1024
#define DD   768
#define HH   12
#define VV   32000
#define LL   2
#define DK   64
#define DFF  3072
#define MM   (BB*SS)
#define QSTR (3*DD)

#define LOGITS_ELEMS ((size_t)BB*SS*VV)
#define AMAP_ELEMS   ((size_t)BB*HH*SS*SS)

// ---------------- scratch ----------------
__device__ float g_h  [MM*DD];     // fp32 residual stream
__device__ float g_ht [MM*DD];     // tf32-rounded copy of h
__device__ float g_qkv[MM*QSTR];   // rounded qkv
__device__ float g_ot [MM*DD];     // rounded attention output
__device__ float g_p  [MM*DD];     // fp32 proj / ff2 output
__device__ float g_fft[MM*DFF];    // rounded relu(ff1)
__device__ float g_wt [(size_t)DD*VV]; // rounded weight, k-major [K][N]
__device__ float g_b3 [QSTR];

__device__ __forceinline__ uint32_t f2tf32(float x) {
    uint32_t r;
    asm("cvt.rna.tf32.f32 %0, %1;" : "=r"(r) : "f"(x));
    return r;
}
__device__ __forceinline__ float tf32r(float x) {
    return __uint_as_float(f2tf32(x));
}
__device__ __forceinline__ void cp_async16(void* sdst, const void* gsrc) {
    uint32_t s = (uint32_t)__cvta_generic_to_shared(sdst);
    asm volatile("cp.async.cg.shared.global [%0], [%1], 16;" :: "r"(s), "l"(gsrc));
}
#define CP_COMMIT() asm volatile("cp.async.commit_group;")
#define CP_WAIT(n)  asm volatile("cp.async.wait_group %0;" :: "n"(n))

#define LDSM4(R0,R1,R2,R3,ADDR) \
    asm volatile("ldmatrix.sync.aligned.m8n8.x4.shared.b16 {%0,%1,%2,%3}, [%4];" \
        : "=r"(R0), "=r"(R1), "=r"(R2), "=r"(R3) : "r"(ADDR))

#define MMA_TF32(ACC, AF, B0, B1) \
    asm volatile("mma.sync.aligned.m16n8k8.row.col.f32.tf32.tf32.f32 " \
        "{%0,%1,%2,%3}, {%4,%5,%6,%7}, {%8,%9}, {%0,%1,%2,%3};" \
        : "+f"((ACC)[0]), "+f"((ACC)[1]), "+f"((ACC)[2]), "+f"((ACC)[3]) \
        : "r"((AF)[0]), "r"((AF)[1]), "r"((AF)[2]), "r"((AF)[3]), \
          "r"(B0), "r"(B1))

// ---------------- weight rounding (linear, k-major preserved) -------------
__global__ void cvt_tf32_kernel(const float4* __restrict__ src,
                                float4* __restrict__ dst, int n4)
{
    int i = blockIdx.x * 256 + threadIdx.x;
    if (i >= n4) return;
    float4 v = src[i];
    v.x = tf32r(v.x); v.y = tf32r(v.y); v.z = tf32r(v.z); v.w = tf32r(v.w);
    dst[i] = v;
}
__global__ void cvt_tf32_cols_kernel(const float* __restrict__ src,
                                     float* __restrict__ dst,
                                     int rows, int cols, int dstr, int coff)
{
    int i = blockIdx.x * 256 + threadIdx.x;
    int c4 = cols >> 2;
    if (i >= rows * c4) return;
    int r = i / c4;
    int c = (i - r*c4) << 2;
    float4 v = *(const float4*)(src + (size_t)r*cols + c);
    v.x = tf32r(v.x); v.y = tf32r(v.y); v.z = tf32r(v.z); v.w = tf32r(v.w);
    *(float4*)(dst + (size_t)r*dstr + coff + c) = v;
}
__global__ void concat3_kernel(const float* __restrict__ a,
                               const float* __restrict__ b,
                               const float* __restrict__ c,
                               float* __restrict__ dst)
{
    int i = blockIdx.x * 256 + threadIdx.x;
    if (i >= QSTR) return;
    dst[i] = (i < DD) ? a[i] : (i < 2*DD ? b[i-DD] : c[i-2*DD]);
}

// ---------------- embedding (fp32 + rounded) -------------------------------
__global__ void embed_kernel(const int* __restrict__ x,
                             const float* __restrict__ emb,
                             const float* __restrict__ pe)
{
    int i = blockIdx.x * 256 + threadIdx.x;
    if (i >= MM*DD) return;
    int row = i / DD;
    int d   = i - row*DD;
    int s   = row & (SS-1);
    int tok = x[row];
    float v = emb[(size_t)tok*DD + d] * 27.712812921102035f + pe[(size_t)s*DD + d];
    g_h[i]  = v;
    g_ht[i] = tf32r(v);
}

// ============ TF32 GEMM (R5 mainloop: 3-stage, A ldmatrix, B scalar LDS) ==
// C[M,N] = A[M,K] @ W[K,N] + bias. BM=BN=128, BK=32.
// mode: bit0 = relu, bit1 = round output to tf32.
#define A_STR 36
#define B_STR 136
#define A_TILE_F (128*A_STR)
#define B_TILE_F (32*B_STR)
#define GEMM_SMEM (3*(A_TILE_F + B_TILE_F)*4)

__global__ __launch_bounds__(256)
void gemm_tf32_kernel(const float* __restrict__ A,
                      const float* __restrict__ W,
                      const float* __restrict__ bias,
                      float* __restrict__ C,
                      int K, int N, int mode)
{
    extern __shared__ float smem[];
    float* As = smem;
    float* Bs = smem + 3*A_TILE_F;

    const int tid    = threadIdx.x;
    const int wid    = tid >> 5;
    const int lane   = tid & 31;
    const int gr     = lane >> 2;
    const int ctg    = lane & 3;
    const int warp_m = wid >> 2;
    const int warp_n = wid & 3;

    const int row0 = blockIdx.x * 128;
    const int col0 = blockIdx.y * 128;

    const int a_m  = tid >> 1;
    const int a_kq = (tid & 1) * 16;
    const int b_k  = tid >> 3;
    const int b_nq = (tid & 7) * 16;

    const float* a_src = A + (size_t)(row0 + a_m)*K + a_kq;
    const float* b_src = W + (size_t)b_k*N + col0 + b_nq;

    const int row_a = ((lane >> 3) & 1) * 8 + (lane & 7);
    const int col_a = (lane >> 4) * 4;

    const uint32_t as_base = (uint32_t)__cvta_generic_to_shared(As);

    float acc[4][4][4] = {};
    const int ntiles = K >> 5;

#define G_ISSUE(tile, slot) do { \
    const float* ag = a_src + (tile)*32; \
    float* ad = &As[(slot)*A_TILE_F + a_m*A_STR + a_kq]; \
    cp_async16(ad,    ag);    cp_async16(ad+4,  ag+4); \
    cp_async16(ad+8,  ag+8);  cp_async16(ad+12, ag+12); \
    const float* bg = b_src + (size_t)(tile)*32*N; \
    float* bd = &Bs[(slot)*B_TILE_F + b_k*B_STR + b_nq]; \
    cp_async16(bd,    bg);    cp_async16(bd+4,  bg+4); \
    cp_async16(bd+8,  bg+8);  cp_async16(bd+12, bg+12); \
} while (0)

    G_ISSUE(0, 0); CP_COMMIT();
    G_ISSUE(1, 1); CP_COMMIT();

    for (int t = 0; t < ntiles; t++) {
        const int s = t % 3;
        CP_WAIT(1);
        __syncthreads();
        {
            const int tn = t + 2;
            if (tn < ntiles) G_ISSUE(tn, tn % 3);
            CP_COMMIT();
        }

        #pragma unroll
        for (int kk = 0; kk < 32; kk += 8) {
            uint32_t af[4][4];
            #pragma unroll
            for (int mt = 0; mt < 4; mt++) {
                uint32_t addr = as_base + 4u*((uint32_t)(s*A_TILE_F)
                              + (uint32_t)((warp_m*64 + mt*16 + row_a)*A_STR)
                              + (uint32_t)(col_a + kk));
                LDSM4(af[mt][0], af[mt][1], af[mt][2], af[mt][3], addr);
            }
            uint32_t bf[4][2];
            #pragma unroll
            for (int nt = 0; nt < 4; nt++) {
                const float* bp = &Bs[s*B_TILE_F + (kk+ctg)*B_STR + warp_n*32 + nt*8 + gr];
                bf[nt][0] = __float_as_uint(bp[0]);
                bf[nt][1] = __float_as_uint(bp[4*B_STR]);
            }
            #pragma unroll
            for (int mt = 0; mt < 4; mt++)
                #pragma unroll
                for (int nt = 0; nt < 4; nt++)
                    MMA_TF32(acc[mt][nt], af[mt], bf[nt][0], bf[nt][1]);
        }
    }
#undef G_ISSUE

    #pragma unroll
    for (int mt = 0; mt < 4; mt++) {
        int r_base = row0 + warp_m*64 + mt*16 + gr;
        #pragma unroll
        for (int nt = 0; nt < 4; nt++) {
            int c_base = col0 + warp_n*32 + nt*8 + 2*ctg;
            float b0 = bias[c_base], b1 = bias[c_base+1];
            float v0 = acc[mt][nt][0] + b0;
            float v1 = acc[mt][nt][1] + b1;
            float v2 = acc[mt][nt][2] + b0;
            float v3 = acc[mt][nt][3] + b1;
            if (mode & 1) {
                v0 = fmaxf(v0, 0.f); v1 = fmaxf(v1, 0.f);
                v2 = fmaxf(v2, 0.f); v3 = fmaxf(v3, 0.f);
            }
            if (mode & 2) {
                v0 = tf32r(v0); v1 = tf32r(v1);
                v2 = tf32r(v2); v3 = tf32r(v3);
            }
            *(float2*)(C + (size_t)r_base*N + c_base)     = make_float2(v0, v1);
            *(float2*)(C + (size_t)(r_base+8)*N + c_base) = make_float2(v2, v3);
        }
    }
}

// ============ attention scores: S = Q @ K^T (operands pre-rounded) ========
#define S_STR 68
#define SCORES_SMEM (2*128*S_STR*4)

__global__ __launch_bounds__(256)
void attn_scores_gemm(const float* __restrict__ qkv,
                      float* __restrict__ amap)
{
    extern __shared__ float smem[];
    float* As = smem;
    float* Bs = smem + 128*S_STR;

    const int tid    = threadIdx.x;
    const int wid    = tid >> 5;
    const int lane   = tid & 31;
    const int gr     = lane >> 2;
    const int ctg    = lane & 3;
    const int warp_m = wid >> 2;
    const int warp_n = wid & 3;

    int idx = blockIdx.x;
    int qb = 0;
    while ((qb+1)*(qb+2)/2 <= idx) qb++;
    int kb = idx - qb*(qb+1)/2;

    const int bh = blockIdx.y;
    const int b  = bh / HH;
    const int hh = bh - b*HH;

    const int row0 = qb * 128;
    const int col0 = kb * 128;

    const float* Qb = qkv + (size_t)(b*SS)*QSTR + hh*DK;
    const float* Kb = Qb + DD;

    const int l_m  = tid >> 1;
    const int l_kq = (tid & 1) * 32;

    {
        const float* ag = Qb + (size_t)(row0 + l_m)*QSTR + l_kq;
        float* ad = &As[l_m*S_STR + l_kq];
        #pragma unroll
        for (int i = 0; i < 8; i++) cp_async16(ad + 4*i, ag + 4*i);
        const float* bg = Kb + (size_t)(col0 + l_m)*QSTR + l_kq;
        float* bd = &Bs[l_m*S_STR + l_kq];
        #pragma unroll
        for (int i = 0; i < 8; i++) cp_async16(bd + 4*i, bg + 4*i);
    }
    CP_COMMIT();
    CP_WAIT(0);
    __syncthreads();

    const int row_a = ((lane >> 3) & 1) * 8 + (lane & 7);
    const int col_a = (lane >> 4) * 4;
    const uint32_t as_base = (uint32_t)__cvta_generic_to_shared(As);
    const uint32_t bs_base = (uint32_t)__cvta_generic_to_shared(Bs);

    float acc[4][4][4] = {};

    #pragma unroll
    for (int kk = 0; kk < 64; kk += 8) {
        uint32_t af[4][4];
        #pragma unroll
        for (int mt = 0; mt < 4; mt++) {
            uint32_t addr = as_base + 4u*(uint32_t)((warp_m*64 + mt*16 + row_a)*S_STR + col_a + kk);
            LDSM4(af[mt][0], af[mt][1], af[mt][2], af[mt][3], addr);
        }
        uint32_t bf[4][2];
        #pragma unroll
        for (int p = 0; p < 2; p++) {
            uint32_t addr = bs_base + 4u*(uint32_t)((warp_n*32 + p*16 + row_a)*S_STR + col_a + kk);
            uint32_t r0, r1, r2, r3;
            LDSM4(r0, r1, r2, r3, addr);
            bf[2*p  ][0] = r0;
            bf[2*p+1][0] = r1;
            bf[2*p  ][1] = r2;
            bf[2*p+1][1] = r3;
        }
        #pragma unroll
        for (int mt = 0; mt < 4; mt++)
            #pragma unroll
            for (int nt = 0; nt < 4; nt++)
                MMA_TF32(acc[mt][nt], af[mt], bf[nt][0], bf[nt][1]);
    }

    float* Sb = amap + (size_t)bh*SS*SS;
    #pragma unroll
    for (int mt = 0; mt < 4; mt++) {
        int r = row0 + warp_m*64 + mt*16 + gr;
        #pragma unroll
        for (int nt = 0; nt < 4; nt++) {
            int c = col0 + warp_n*32 + nt*8 + 2*ctg;
            *(float2*)(Sb + (size_t)r*SS + c) =
                make_float2(acc[mt][nt][0]*0.125f, acc[mt][nt][1]*0.125f);
            *(float2*)(Sb + (size_t)(r+8)*SS + c) =
                make_float2(acc[mt][nt][2]*0.125f, acc[mt][nt][3]*0.125f);
        }
    }
}

// ============ softmax rows, in place ======================================
__global__ void softmax_rows(float* __restrict__ amap)
{
    const int qpos = blockIdx.x;
    const int bh   = blockIdx.y;
    const int tid  = threadIdx.x;
    const int wid  = tid >> 5;
    const int lane = tid & 31;

    float* row = amap + ((size_t)bh*SS + qpos)*SS;

    __shared__ float sc[SS];
    __shared__ float red[8];
    __shared__ float bcast;

    float m = -1e30f;
    for (int k = tid; k <= qpos; k += 256) {
        float v = row[k];
        sc[k] = v;
        m = fmaxf(m, v);
    }
    #pragma unroll
    for (int o = 16; o > 0; o >>= 1) m = fmaxf(m, __shfl_xor_sync(0xffffffffu, m, o));
    if (lane == 0) red[wid] = m;
    __syncthreads();
    if (tid == 0) {
        float mm = red[0];
        #pragma unroll
        for (int i = 1; i < 8; i++) mm = fmaxf(mm, red[i]);
        bcast = mm;
    }
    __syncthreads();
    m = bcast;

    float s = 0.0f;
    for (int k = tid; k <= qpos; k += 256) {
        float e = __expf(sc[k] - m);
        sc[k] = e;
        s += e;
    }
    #pragma unroll
    for (int o = 16; o > 0; o >>= 1) s += __shfl_xor_sync(0xffffffffu, s, o);
    if (lane == 0) red[wid] = s;
    __syncthreads();
    if (tid == 0) {
        float ss = red[0];
        #pragma unroll
        for (int i = 1; i < 8; i++) ss += red[i];
        bcast = 1.0f / ss;
    }
    __syncthreads();
    float inv = bcast;

    for (int k = tid; k < SS; k += 256)
        row[k] = (k <= qpos) ? sc[k] * inv : 0.0f;
}

// ============ attn_o: O = amap @ V, rounded output ========================
#define AS_PAD 36
#define BO_PAD 68
#define ATTN_SMEM ((2*128*AS_PAD + 2*32*BO_PAD)*4)
__global__ __launch_bounds__(256)
void attn_o_mma_kernel(const float* __restrict__ amap,
                       const float* __restrict__ qkv,
                       float* __restrict__ O)
{
    extern __shared__ float smem[];
    float* As = smem;
    float* Bs = smem + 2*128*AS_PAD;
#define ASM(b,m,k) As[((b)*128+(m))*AS_PAD+(k)]
#define BSM(b,k,n) Bs[((b)*32+(k))*BO_PAD+(n)]

    const int tid    = threadIdx.x;
    const int wid    = tid >> 5;
    const int lane   = tid & 31;
    const int gr     = lane >> 2;
    const int ctg    = lane & 3;
    const int warp_m = wid & 3;
    const int warp_n = wid >> 2;

    const int row0 = blockIdx.x * 128;
    const int bh   = blockIdx.y;
    const int b    = bh / HH;
    const int hh   = bh - b*HH;

    const float* Arow = amap + (size_t)bh*SS*SS;
    const float* Vb   = qkv + (size_t)(b*SS)*QSTR + 2*DD + hh*DK;

    const int a_m  = tid >> 1;
    const int a_kq = (tid & 1) * 16;
    const int b_k  = tid >> 3;
    const int b_nq = (tid & 7) * 8;

    const float* a_src = Arow + (size_t)(row0 + a_m)*SS + a_kq;
    const float* b_src = Vb + (size_t)b_k*QSTR + b_nq;

    float acc[2][4][4] = {};
    const int nt = (row0 + 128) >> 5;

    #pragma unroll
    for (int i = 0; i < 4; i++) cp_async16(&ASM(0, a_m, a_kq + 4*i), a_src + 4*i);
    #pragma unroll
    for (int i = 0; i < 2; i++) cp_async16(&BSM(0, b_k, b_nq + 4*i), b_src + 4*i);
    CP_COMMIT();

    for (int t = 0; t < nt; t++) {
        const int cur = t & 1;
        if (t + 1 < nt) {
            const int nb = cur ^ 1;
            const int k0 = (t+1) << 5;
            #pragma unroll
            for (int i = 0; i < 4; i++)
                cp_async16(&ASM(nb, a_m, a_kq + 4*i), a_src + k0 + 4*i);
            #pragma unroll
            for (int i = 0; i < 2; i++)
                cp_async16(&BSM(nb, b_k, b_nq + 4*i), b_src + (size_t)k0*QSTR + 4*i);
            CP_COMMIT();
            CP_WAIT(1);
        } else {
            CP_WAIT(0);
        }
        __syncthreads();

        #pragma unroll
        for (int kk = 0; kk < 32; kk += 8) {
            uint32_t af[2][4];
            #pragma unroll
            for (int mt = 0; mt < 2; mt++) {
                int mb = warp_m*32 + mt*16;
                af[mt][0] = f2tf32(ASM(cur, mb+gr,   kk+ctg));
                af[mt][1] = f2tf32(ASM(cur, mb+gr+8, kk+ctg));
                af[mt][2] = f2tf32(ASM(cur, mb+gr,   kk+ctg+4));
                af[mt][3] = f2tf32(ASM(cur, mb+gr+8, kk+ctg+4));
            }
            uint32_t bf[4][2];
            #pragma unroll
            for (int ntl = 0; ntl < 4; ntl++) {
                int nb = warp_n*32 + ntl*8;
                bf[ntl][0] = __float_as_uint(BSM(cur, kk+ctg,   nb+gr));
                bf[ntl][1] = __float_as_uint(BSM(cur, kk+ctg+4, nb+gr));
            }
            #pragma unroll
            for (int mt = 0; mt < 2; mt++)
                #pragma unroll
                for (int ntl = 0; ntl < 4; ntl++)
                    MMA_TF32(acc[mt][ntl], af[mt], bf[ntl][0], bf[ntl][1]);
        }
        __syncthreads();
    }

    #pragma unroll
    for (int mt = 0; mt < 2; mt++) {
        int r = row0 + warp_m*32 + mt*16 + gr;
        #pragma unroll
        for (int ntl = 0; ntl < 4; ntl++) {
            int c = warp_n*32 + ntl*8 + 2*ctg;
            float* dst = O + (size_t)(b*SS + r)*DD + hh*DK + c;
            *(float2*)dst = make_float2(tf32r(acc[mt][ntl][0]), tf32r(acc[mt][ntl][1]));
            *(float2*)(dst + 8*DD) = make_float2(tf32r(acc[mt][ntl][2]), tf32r(acc[mt][ntl][3]));
        }
    }
#undef ASM
#undef BSM
}

// ---------------- residual add + layernorm (fp32 + rounded outputs) -------
__global__ void add_ln_kernel(const float* __restrict__ res,
                              const float* __restrict__ x,
                              const float* __restrict__ g,
                              const float* __restrict__ be,
                              float* __restrict__ out,
                              float* __restrict__ outt)
{
    const int row = blockIdx.x;
    const int tid = threadIdx.x;
    __shared__ float buf[DD];
    __shared__ float red[256];

    float s = 0.0f;
    for (int d = tid; d < DD; d += 256) {
        float v = res[(size_t)row*DD + d] + x[(size_t)row*DD + d];
        buf[d] = v;
        s += v;
    }
    red[tid] = s; __syncthreads();
    for (int t = 128; t > 0; t >>= 1) {
        if (tid < t) red[tid] += red[tid+t];
        __syncthreads();
    }
    float mean = red[0] * (1.0f/DD);
    __syncthreads();

    float vs = 0.0f;
    for (int d = tid; d < DD; d += 256) {
        float dv = buf[d] - mean;
        vs += dv*dv;
    }
    red[tid] = vs; __syncthreads();
    for (int t = 128; t > 0; t >>= 1) {
        if (tid < t) red[tid] += red[tid+t];
        __syncthreads();
    }
    float rstd = rsqrtf(red[0] * (1.0f/DD) + 1e-5f);

    for (int d = tid; d < DD; d += 256) {
        float v = (buf[d] - mean)*rstd*g[d] + be[d];
        out [(size_t)row*DD + d] = v;
        outt[(size_t)row*DD + d] = tf32r(v);
    }
}

// ---------------------------------------------------------------------------
static inline void cvtw(const float* src, float* dst, size_t n) {
    int n4 = (int)(n >> 2);
    cvt_tf32_kernel<<<(n4 + 255)/256, 256>>>((const float4*)src, (float4*)dst, n4);
}

extern "C" void kernel_launch(void* const* d_in, const int* in_sizes, int n_in,
                              void* d_out, int out_size)
{
    (void)in_sizes; (void)n_in; (void)out_size;

    const int*   x    = (const int*)  d_in[0];
    const float* emb  = (const float*)d_in[2];
    const float* pe   = (const float*)d_in[3];
    const float* wq   = (const float*)d_in[4];
    const float* bq   = (const float*)d_in[5];
    const float* wk   = (const float*)d_in[6];
    const float* bk   = (const float*)d_in[7];
    const float* wv   = (const float*)d_in[8];
    const float* bv   = (const float*)d_in[9];
    const float* wo   = (const float*)d_in[10];
    const float* bo   = (const float*)d_in[11];
    const float* w1   = (const float*)d_in[12];
    const float* b1   = (const float*)d_in[13];
    const float* w2   = (const float*)d_in[14];
    const float* b2   = (const float*)d_in[15];
    const float* g1   = (const float*)d_in[16];
    const float* be1  = (const float*)d_in[17];
    const float* g2   = (const float*)d_in[18];
    const float* be2  = (const float*)d_in[19];
    const float* wout = (const float*)d_in[20];
    const float* bout = (const float*)d_in[21];
    float* out = (float*)d_out;

    static float *p_h=nullptr,*p_ht,*p_qkv,*p_ot,*p_p,*p_fft,*p_wt,*p_b3;
    if (!p_h) {
        void* p;
        cudaGetSymbolAddress(&p, g_h);   p_h   = (float*)p;
        cudaGetSymbolAddress(&p, g_ht);  p_ht  = (float*)p;
        cudaGetSymbolAddress(&p, g_qkv); p_qkv = (float*)p;
        cudaGetSymbolAddress(&p, g_ot);  p_ot  = (float*)p;
        cudaGetSymbolAddress(&p, g_p);   p_p   = (float*)p;
        cudaGetSymbolAddress(&p, g_fft); p_fft = (float*)p;
        cudaGetSymbolAddress(&p, g_wt);  p_wt  = (float*)p;
        cudaGetSymbolAddress(&p, g_b3);  p_b3  = (float*)p;
        cudaFuncSetAttribute(gemm_tf32_kernel,
            cudaFuncAttributeMaxDynamicSharedMemorySize, GEMM_SMEM);
        cudaFuncSetAttribute(attn_scores_gemm,
            cudaFuncAttributeMaxDynamicSharedMemorySize, SCORES_SMEM);
        cudaFuncSetAttribute(attn_o_mma_kernel,
            cudaFuncAttributeMaxDynamicSharedMemorySize, ATTN_SMEM);
    }

    embed_kernel<<<(MM*DD + 255)/256, 256>>>(x, emb, pe);

    const int wblk = (DD*DD/4 + 255)/256;

    for (int l = 0; l < LL; l++) {
        const float* wq_l = wq + (size_t)l*DD*DD;
        const float* wk_l = wk + (size_t)l*DD*DD;
        const float* wv_l = wv + (size_t)l*DD*DD;
        const float* wo_l = wo + (size_t)l*DD*DD;
        const float* w1_l = w1 + (size_t)l*DD*DFF;
        const float* w2_l = w2 + (size_t)l*DFF*DD;

        // ---- fused QKV ----
        cvt_tf32_cols_kernel<<<wblk, 256>>>(wq_l, p_wt, DD, DD, QSTR, 0);
        cvt_tf32_cols_kernel<<<wblk, 256>>>(wk_l, p_wt, DD, DD, QSTR, DD);
        cvt_tf32_cols_kernel<<<wblk, 256>>>(wv_l, p_wt, DD, DD, QSTR, 2*DD);
        concat3_kernel<<<(QSTR+255)/256, 256>>>(bq + l*DD, bk + l*DD, bv + l*DD, p_b3);
        dim3 gqkv(MM/128, QSTR/128);
        gemm_tf32_kernel<<<gqkv, 256, GEMM_SMEM>>>(p_ht, p_wt, p_b3, p_qkv, DD, QSTR, 2);

        // ---- attention ----
        float* amap_l = out + LOGITS_ELEMS + (size_t)l*AMAP_ELEMS;
        dim3 gsc(36, BB*HH);
        attn_scores_gemm<<<gsc, 256, SCORES_SMEM>>>(p_qkv, amap_l);
        dim3 gsm(SS, BB*HH);
        softmax_rows<<<gsm, 256>>>(amap_l);
        dim3 gao(SS/128, BB*HH);
        attn_o_mma_kernel<<<gao, 256, ATTN_SMEM>>>(amap_l, p_qkv, p_ot);

        // ---- output projection ----
        cvtw(wo_l, p_wt, (size_t)DD*DD);
        dim3 gproj(MM/128, DD/128);
        gemm_tf32_kernel<<<gproj, 256, GEMM_SMEM>>>(p_ot, p_wt, bo + l*DD, p_p, DD, DD, 0);
        add_ln_kernel<<<MM, 256>>>(p_h, p_p, g1 + l*DD, be1 + l*DD, p_h, p_ht);

        // ---- FFN ----
        cvtw(w1_l, p_wt, (size_t)DD*DFF);
        dim3 gff1(MM/128, DFF/128);
        gemm_tf32_kernel<<<gff1, 256, GEMM_SMEM>>>(p_ht, p_wt, b1 + l*DFF, p_fft, DD, DFF, 3);

        cvtw(w2_l, p_wt, (size_t)DFF*DD);
        dim3 gff2(MM/128, DD/128);
        gemm_tf32_kernel<<<gff2, 256, GEMM_SMEM>>>(p_fft, p_wt, b2 + l*DD, p_p, DFF, DD, 0);
        add_ln_kernel<<<MM, 256>>>(p_h, p_p, g2 + l*DD, be2 + l*DD, p_h, p_ht);
    }

    // ---- logits ----
    cvtw(wout, p_wt, (size_t)DD*VV);
    dim3 glog(MM/128, VV/128);
    gemm_tf32_kernel<<<glog, 256, GEMM_SMEM>>>(p_ht, p_wt, bout, out, DD, VV, 0);
}

// round 9
// speedup vs baseline: 1.6068x; 1.0984x over previous
#include <cuda_runtime.h>
#include <math.h>
#include <stdint.h>

#define BB   4
#define SS   1024
#define DD   768
#define HH   12
#define VV   32000
#define LL   2
#define DK   64
#define DFF  3072
#define MM   (BB*SS)
#define QSTR (3*DD)

#define LOGITS_ELEMS ((size_t)BB*SS*VV)
#define AMAP_ELEMS   ((size_t)BB*HH*SS*SS)

// ---------------- scratch ----------------
__device__ float g_h  [MM*DD];
__device__ float g_ht [MM*DD];
__device__ float g_qkv[MM*QSTR];
__device__ float g_ot [MM*DD];
__device__ float g_p  [MM*DD];
__device__ float g_fft[MM*DFF];
__device__ float g_wt [(size_t)DD*VV];
__device__ float g_b3 [QSTR];

__device__ __forceinline__ uint32_t f2tf32(float x) {
    uint32_t r;
    asm("cvt.rna.tf32.f32 %0, %1;" : "=r"(r) : "f"(x));
    return r;
}
__device__ __forceinline__ float tf32r(float x) {
    return __uint_as_float(f2tf32(x));
}
__device__ __forceinline__ void cp_async16(void* sdst, const void* gsrc) {
    uint32_t s = (uint32_t)__cvta_generic_to_shared(sdst);
    asm volatile("cp.async.cg.shared.global [%0], [%1], 16;" :: "r"(s), "l"(gsrc));
}
#define CP_COMMIT() asm volatile("cp.async.commit_group;")
#define CP_WAIT(n)  asm volatile("cp.async.wait_group %0;" :: "n"(n))

#define LDSM4(R0,R1,R2,R3,ADDR) \
    asm volatile("ldmatrix.sync.aligned.m8n8.x4.shared.b16 {%0,%1,%2,%3}, [%4];" \
        : "=r"(R0), "=r"(R1), "=r"(R2), "=r"(R3) : "r"(ADDR))

#define MMA_TF32(ACC, AF, B0, B1) \
    asm volatile("mma.sync.aligned.m16n8k8.row.col.f32.tf32.tf32.f32 " \
        "{%0,%1,%2,%3}, {%4,%5,%6,%7}, {%8,%9}, {%0,%1,%2,%3};" \
        : "+f"((ACC)[0]), "+f"((ACC)[1]), "+f"((ACC)[2]), "+f"((ACC)[3]) \
        : "r"((AF)[0]), "r"((AF)[1]), "r"((AF)[2]), "r"((AF)[3]), \
          "r"(B0), "r"(B1))

// ---------------- weight rounding ----------------
__global__ void cvt_tf32_kernel(const float4* __restrict__ src,
                                float4* __restrict__ dst, int n4)
{
    int i = blockIdx.x * 256 + threadIdx.x;
    if (i >= n4) return;
    float4 v = src[i];
    v.x = tf32r(v.x); v.y = tf32r(v.y); v.z = tf32r(v.z); v.w = tf32r(v.w);
    dst[i] = v;
}
__global__ void cvt_tf32_cols_kernel(const float* __restrict__ src,
                                     float* __restrict__ dst,
                                     int rows, int cols, int dstr, int coff)
{
    int i = blockIdx.x * 256 + threadIdx.x;
    int c4 = cols >> 2;
    if (i >= rows * c4) return;
    int r = i / c4;
    int c = (i - r*c4) << 2;
    float4 v = *(const float4*)(src + (size_t)r*cols + c);
    v.x = tf32r(v.x); v.y = tf32r(v.y); v.z = tf32r(v.z); v.w = tf32r(v.w);
    *(float4*)(dst + (size_t)r*dstr + coff + c) = v;
}
__global__ void concat3_kernel(const float* __restrict__ a,
                               const float* __restrict__ b,
                               const float* __restrict__ c,
                               float* __restrict__ dst)
{
    int i = blockIdx.x * 256 + threadIdx.x;
    if (i >= QSTR) return;
    dst[i] = (i < DD) ? a[i] : (i < 2*DD ? b[i-DD] : c[i-2*DD]);
}

// ---------------- embedding ----------------
__global__ void embed_kernel(const int* __restrict__ x,
                             const float* __restrict__ emb,
                             const float* __restrict__ pe)
{
    int i = blockIdx.x * 256 + threadIdx.x;
    if (i >= MM*DD) return;
    int row = i / DD;
    int d   = i - row*DD;
    int s   = row & (SS-1);
    int tok = x[row];
    float v = emb[(size_t)tok*DD + d] * 27.712812921102035f + pe[(size_t)s*DD + d];
    g_h[i]  = v;
    g_ht[i] = tf32r(v);
}

// ============ TF32 GEMM: BM=128 BN=256 BK=32, 512 threads, 3-stage ========
// C[M,N] = A[M,K] @ W[K,N] + bias. N must be %256. mode: bit0 relu, bit1 round.
#define A_STR 36
#define B_STR 264
#define A_TILE_F (128*A_STR)
#define B_TILE_F (32*B_STR)
#define GEMM_SMEM (3*(A_TILE_F + B_TILE_F)*4)

__global__ __launch_bounds__(512, 1)
void gemm_tf32_kernel(const float* __restrict__ A,
                      const float* __restrict__ W,
                      const float* __restrict__ bias,
                      float* __restrict__ C,
                      int K, int N, int mode)
{
    extern __shared__ float smem[];
    float* As = smem;
    float* Bs = smem + 3*A_TILE_F;

    const int tid    = threadIdx.x;
    const int wid    = tid >> 5;
    const int lane   = tid & 31;
    const int gr     = lane >> 2;
    const int ctg    = lane & 3;
    const int warp_m = wid >> 3;   // 0..1 -> 64 rows
    const int warp_n = wid & 7;    // 0..7 -> 32 cols

    const int row0 = blockIdx.x * 128;
    const int col0 = blockIdx.y * 256;

    // loaders (512 threads)
    const int a_m  = tid >> 2;          // 0..127
    const int a_kq = (tid & 3) * 8;     // 0,8,16,24
    const int b_k  = tid >> 4;          // 0..31
    const int b_nq = (tid & 15) * 16;   // 0..240

    const float* a_src = A + (size_t)(row0 + a_m)*K + a_kq;
    const float* b_src = W + (size_t)b_k*N + col0 + b_nq;

    const int row_a = ((lane >> 3) & 1) * 8 + (lane & 7);
    const int col_a = (lane >> 4) * 4;

    const uint32_t as_base = (uint32_t)__cvta_generic_to_shared(As);

    float acc[4][4][4] = {};
    const int ntiles = K >> 5;

#define G_ISSUE(tile, slot) do { \
    const float* ag = a_src + (tile)*32; \
    float* ad = &As[(slot)*A_TILE_F + a_m*A_STR + a_kq]; \
    cp_async16(ad,   ag);   cp_async16(ad+4, ag+4); \
    const float* bg = b_src + (size_t)(tile)*32*N; \
    float* bd = &Bs[(slot)*B_TILE_F + b_k*B_STR + b_nq]; \
    cp_async16(bd,    bg);    cp_async16(bd+4,  bg+4); \
    cp_async16(bd+8,  bg+8);  cp_async16(bd+12, bg+12); \
} while (0)

    G_ISSUE(0, 0); CP_COMMIT();
    G_ISSUE(1, 1); CP_COMMIT();

    for (int t = 0; t < ntiles; t++) {
        const int s = t % 3;
        CP_WAIT(1);
        __syncthreads();
        {
            const int tn = t + 2;
            if (tn < ntiles) G_ISSUE(tn, tn % 3);
            CP_COMMIT();
        }

        #pragma unroll
        for (int kk = 0; kk < 32; kk += 8) {
            uint32_t af[4][4];
            #pragma unroll
            for (int mt = 0; mt < 4; mt++) {
                uint32_t addr = as_base + 4u*((uint32_t)(s*A_TILE_F)
                              + (uint32_t)((warp_m*64 + mt*16 + row_a)*A_STR)
                              + (uint32_t)(col_a + kk));
                LDSM4(af[mt][0], af[mt][1], af[mt][2], af[mt][3], addr);
            }
            uint32_t bf[4][2];
            #pragma unroll
            for (int nt = 0; nt < 4; nt++) {
                const float* bp = &Bs[s*B_TILE_F + (kk+ctg)*B_STR + warp_n*32 + nt*8 + gr];
                bf[nt][0] = __float_as_uint(bp[0]);
                bf[nt][1] = __float_as_uint(bp[4*B_STR]);
            }
            #pragma unroll
            for (int mt = 0; mt < 4; mt++)
                #pragma unroll
                for (int nt = 0; nt < 4; nt++)
                    MMA_TF32(acc[mt][nt], af[mt], bf[nt][0], bf[nt][1]);
        }
    }
#undef G_ISSUE

    #pragma unroll
    for (int mt = 0; mt < 4; mt++) {
        int r_base = row0 + warp_m*64 + mt*16 + gr;
        #pragma unroll
        for (int nt = 0; nt < 4; nt++) {
            int c_base = col0 + warp_n*32 + nt*8 + 2*ctg;
            float b0 = bias[c_base], b1 = bias[c_base+1];
            float v0 = acc[mt][nt][0] + b0;
            float v1 = acc[mt][nt][1] + b1;
            float v2 = acc[mt][nt][2] + b0;
            float v3 = acc[mt][nt][3] + b1;
            if (mode & 1) {
                v0 = fmaxf(v0, 0.f); v1 = fmaxf(v1, 0.f);
                v2 = fmaxf(v2, 0.f); v3 = fmaxf(v3, 0.f);
            }
            if (mode & 2) {
                v0 = tf32r(v0); v1 = tf32r(v1);
                v2 = tf32r(v2); v3 = tf32r(v3);
            }
            *(float2*)(C + (size_t)r_base*N + c_base)     = make_float2(v0, v1);
            *(float2*)(C + (size_t)(r_base+8)*N + c_base) = make_float2(v2, v3);
        }
    }
}

// ============ attention scores: S = Q @ K^T ===============================
#define S_STR 68
#define SCORES_SMEM (2*128*S_STR*4)

__global__ __launch_bounds__(256)
void attn_scores_gemm(const float* __restrict__ qkv,
                      float* __restrict__ amap)
{
    extern __shared__ float smem[];
    float* As = smem;
    float* Bs = smem + 128*S_STR;

    const int tid    = threadIdx.x;
    const int wid    = tid >> 5;
    const int lane   = tid & 31;
    const int gr     = lane >> 2;
    const int ctg    = lane & 3;
    const int warp_m = wid >> 2;
    const int warp_n = wid & 3;

    int idx = blockIdx.x;
    int qb = 0;
    while ((qb+1)*(qb+2)/2 <= idx) qb++;
    int kb = idx - qb*(qb+1)/2;

    const int bh = blockIdx.y;
    const int b  = bh / HH;
    const int hh = bh - b*HH;

    const int row0 = qb * 128;
    const int col0 = kb * 128;

    const float* Qb = qkv + (size_t)(b*SS)*QSTR + hh*DK;
    const float* Kb = Qb + DD;

    const int l_m  = tid >> 1;
    const int l_kq = (tid & 1) * 32;

    {
        const float* ag = Qb + (size_t)(row0 + l_m)*QSTR + l_kq;
        float* ad = &As[l_m*S_STR + l_kq];
        #pragma unroll
        for (int i = 0; i < 8; i++) cp_async16(ad + 4*i, ag + 4*i);
        const float* bg = Kb + (size_t)(col0 + l_m)*QSTR + l_kq;
        float* bd = &Bs[l_m*S_STR + l_kq];
        #pragma unroll
        for (int i = 0; i < 8; i++) cp_async16(bd + 4*i, bg + 4*i);
    }
    CP_COMMIT();
    CP_WAIT(0);
    __syncthreads();

    const int row_a = ((lane >> 3) & 1) * 8 + (lane & 7);
    const int col_a = (lane >> 4) * 4;
    const uint32_t as_base = (uint32_t)__cvta_generic_to_shared(As);
    const uint32_t bs_base = (uint32_t)__cvta_generic_to_shared(Bs);

    float acc[4][4][4] = {};

    #pragma unroll
    for (int kk = 0; kk < 64; kk += 8) {
        uint32_t af[4][4];
        #pragma unroll
        for (int mt = 0; mt < 4; mt++) {
            uint32_t addr = as_base + 4u*(uint32_t)((warp_m*64 + mt*16 + row_a)*S_STR + col_a + kk);
            LDSM4(af[mt][0], af[mt][1], af[mt][2], af[mt][3], addr);
        }
        uint32_t bf[4][2];
        #pragma unroll
        for (int p = 0; p < 2; p++) {
            uint32_t addr = bs_base + 4u*(uint32_t)((warp_n*32 + p*16 + row_a)*S_STR + col_a + kk);
            uint32_t r0, r1, r2, r3;
            LDSM4(r0, r1, r2, r3, addr);
            bf[2*p  ][0] = r0;
            bf[2*p+1][0] = r1;
            bf[2*p  ][1] = r2;
            bf[2*p+1][1] = r3;
        }
        #pragma unroll
        for (int mt = 0; mt < 4; mt++)
            #pragma unroll
            for (int nt = 0; nt < 4; nt++)
                MMA_TF32(acc[mt][nt], af[mt], bf[nt][0], bf[nt][1]);
    }

    float* Sb = amap + (size_t)bh*SS*SS;
    #pragma unroll
    for (int mt = 0; mt < 4; mt++) {
        int r = row0 + warp_m*64 + mt*16 + gr;
        #pragma unroll
        for (int nt = 0; nt < 4; nt++) {
            int c = col0 + warp_n*32 + nt*8 + 2*ctg;
            *(float2*)(Sb + (size_t)r*SS + c) =
                make_float2(acc[mt][nt][0]*0.125f, acc[mt][nt][1]*0.125f);
            *(float2*)(Sb + (size_t)(r+8)*SS + c) =
                make_float2(acc[mt][nt][2]*0.125f, acc[mt][nt][3]*0.125f);
        }
    }
}

// ============ softmax rows, in place ======================================
__global__ void softmax_rows(float* __restrict__ amap)
{
    const int qpos = blockIdx.x;
    const int bh   = blockIdx.y;
    const int tid  = threadIdx.x;
    const int wid  = tid >> 5;
    const int lane = tid & 31;

    float* row = amap + ((size_t)bh*SS + qpos)*SS;

    __shared__ float sc[SS];
    __shared__ float red[8];
    __shared__ float bcast;

    float m = -1e30f;
    for (int k = tid; k <= qpos; k += 256) {
        float v = row[k];
        sc[k] = v;
        m = fmaxf(m, v);
    }
    #pragma unroll
    for (int o = 16; o > 0; o >>= 1) m = fmaxf(m, __shfl_xor_sync(0xffffffffu, m, o));
    if (lane == 0) red[wid] = m;
    __syncthreads();
    if (tid == 0) {
        float mm = red[0];
        #pragma unroll
        for (int i = 1; i < 8; i++) mm = fmaxf(mm, red[i]);
        bcast = mm;
    }
    __syncthreads();
    m = bcast;

    float s = 0.0f;
    for (int k = tid; k <= qpos; k += 256) {
        float e = __expf(sc[k] - m);
        sc[k] = e;
        s += e;
    }
    #pragma unroll
    for (int o = 16; o > 0; o >>= 1) s += __shfl_xor_sync(0xffffffffu, s, o);
    if (lane == 0) red[wid] = s;
    __syncthreads();
    if (tid == 0) {
        float ss = red[0];
        #pragma unroll
        for (int i = 1; i < 8; i++) ss += red[i];
        bcast = 1.0f / ss;
    }
    __syncthreads();
    float inv = bcast;

    for (int k = tid; k < SS; k += 256)
        row[k] = (k <= qpos) ? sc[k] * inv : 0.0f;
}

// ============ attn_o: O = amap @ V, rounded output ========================
#define AS_PAD 36
#define BO_PAD 68
#define ATTN_SMEM ((2*128*AS_PAD + 2*32*BO_PAD)*4)
__global__ __launch_bounds__(256)
void attn_o_mma_kernel(const float* __restrict__ amap,
                       const float* __restrict__ qkv,
                       float* __restrict__ O)
{
    extern __shared__ float smem[];
    float* As = smem;
    float* Bs = smem + 2*128*AS_PAD;
#define ASM(b,m,k) As[((b)*128+(m))*AS_PAD+(k)]
#define BSM(b,k,n) Bs[((b)*32+(k))*BO_PAD+(n)]

    const int tid    = threadIdx.x;
    const int wid    = tid >> 5;
    const int lane   = tid & 31;
    const int gr     = lane >> 2;
    const int ctg    = lane & 3;
    const int warp_m = wid & 3;
    const int warp_n = wid >> 2;

    const int row0 = blockIdx.x * 128;
    const int bh   = blockIdx.y;
    const int b    = bh / HH;
    const int hh   = bh - b*HH;

    const float* Arow = amap + (size_t)bh*SS*SS;
    const float* Vb   = qkv + (size_t)(b*SS)*QSTR + 2*DD + hh*DK;

    const int a_m  = tid >> 1;
    const int a_kq = (tid & 1) * 16;
    const int b_k  = tid >> 3;
    const int b_nq = (tid & 7) * 8;

    const float* a_src = Arow + (size_t)(row0 + a_m)*SS + a_kq;
    const float* b_src = Vb + (size_t)b_k*QSTR + b_nq;

    float acc[2][4][4] = {};
    const int nt = (row0 + 128) >> 5;

    #pragma unroll
    for (int i = 0; i < 4; i++) cp_async16(&ASM(0, a_m, a_kq + 4*i), a_src + 4*i);
    #pragma unroll
    for (int i = 0; i < 2; i++) cp_async16(&BSM(0, b_k, b_nq + 4*i), b_src + 4*i);
    CP_COMMIT();

    for (int t = 0; t < nt; t++) {
        const int cur = t & 1;
        if (t + 1 < nt) {
            const int nb = cur ^ 1;
            const int k0 = (t+1) << 5;
            #pragma unroll
            for (int i = 0; i < 4; i++)
                cp_async16(&ASM(nb, a_m, a_kq + 4*i), a_src + k0 + 4*i);
            #pragma unroll
            for (int i = 0; i < 2; i++)
                cp_async16(&BSM(nb, b_k, b_nq + 4*i), b_src + (size_t)k0*QSTR + 4*i);
            CP_COMMIT();
            CP_WAIT(1);
        } else {
            CP_WAIT(0);
        }
        __syncthreads();

        #pragma unroll
        for (int kk = 0; kk < 32; kk += 8) {
            uint32_t af[2][4];
            #pragma unroll
            for (int mt = 0; mt < 2; mt++) {
                int mb = warp_m*32 + mt*16;
                af[mt][0] = f2tf32(ASM(cur, mb+gr,   kk+ctg));
                af[mt][1] = f2tf32(ASM(cur, mb+gr+8, kk+ctg));
                af[mt][2] = f2tf32(ASM(cur, mb+gr,   kk+ctg+4));
                af[mt][3] = f2tf32(ASM(cur, mb+gr+8, kk+ctg+4));
            }
            uint32_t bf[4][2];
            #pragma unroll
            for (int ntl = 0; ntl < 4; ntl++) {
                int nb = warp_n*32 + ntl*8;
                bf[ntl][0] = __float_as_uint(BSM(cur, kk+ctg,   nb+gr));
                bf[ntl][1] = __float_as_uint(BSM(cur, kk+ctg+4, nb+gr));
            }
            #pragma unroll
            for (int mt = 0; mt < 2; mt++)
                #pragma unroll
                for (int ntl = 0; ntl < 4; ntl++)
                    MMA_TF32(acc[mt][ntl], af[mt], bf[ntl][0], bf[ntl][1]);
        }
        __syncthreads();
    }

    #pragma unroll
    for (int mt = 0; mt < 2; mt++) {
        int r = row0 + warp_m*32 + mt*16 + gr;
        #pragma unroll
        for (int ntl = 0; ntl < 4; ntl++) {
            int c = warp_n*32 + ntl*8 + 2*ctg;
            float* dst = O + (size_t)(b*SS + r)*DD + hh*DK + c;
            *(float2*)dst = make_float2(tf32r(acc[mt][ntl][0]), tf32r(acc[mt][ntl][1]));
            *(float2*)(dst + 8*DD) = make_float2(tf32r(acc[mt][ntl][2]), tf32r(acc[mt][ntl][3]));
        }
    }
#undef ASM
#undef BSM
}

// ---------------- residual add + layernorm --------------------------------
__global__ void add_ln_kernel(const float* __restrict__ res,
                              const float* __restrict__ x,
                              const float* __restrict__ g,
                              const float* __restrict__ be,
                              float* __restrict__ out,
                              float* __restrict__ outt)
{
    const int row = blockIdx.x;
    const int tid = threadIdx.x;
    __shared__ float buf[DD];
    __shared__ float red[256];

    float s = 0.0f;
    for (int d = tid; d < DD; d += 256) {
        float v = res[(size_t)row*DD + d] + x[(size_t)row*DD + d];
        buf[d] = v;
        s += v;
    }
    red[tid] = s; __syncthreads();
    for (int t = 128; t > 0; t >>= 1) {
        if (tid < t) red[tid] += red[tid+t];
        __syncthreads();
    }
    float mean = red[0] * (1.0f/DD);
    __syncthreads();

    float vs = 0.0f;
    for (int d = tid; d < DD; d += 256) {
        float dv = buf[d] - mean;
        vs += dv*dv;
    }
    red[tid] = vs; __syncthreads();
    for (int t = 128; t > 0; t >>= 1) {
        if (tid < t) red[tid] += red[tid+t];
        __syncthreads();
    }
    float rstd = rsqrtf(red[0] * (1.0f/DD) + 1e-5f);

    for (int d = tid; d < DD; d += 256) {
        float v = (buf[d] - mean)*rstd*g[d] + be[d];
        out [(size_t)row*DD + d] = v;
        outt[(size_t)row*DD + d] = tf32r(v);
    }
}

// ---------------------------------------------------------------------------
static inline void cvtw(const float* src, float* dst, size_t n) {
    int n4 = (int)(n >> 2);
    cvt_tf32_kernel<<<(n4 + 255)/256, 256>>>((const float4*)src, (float4*)dst, n4);
}

extern "C" void kernel_launch(void* const* d_in, const int* in_sizes, int n_in,
                              void* d_out, int out_size)
{
    (void)in_sizes; (void)n_in; (void)out_size;

    const int*   x    = (const int*)  d_in[0];
    const float* emb  = (const float*)d_in[2];
    const float* pe   = (const float*)d_in[3];
    const float* wq   = (const float*)d_in[4];
    const float* bq   = (const float*)d_in[5];
    const float* wk   = (const float*)d_in[6];
    const float* bk   = (const float*)d_in[7];
    const float* wv   = (const float*)d_in[8];
    const float* bv   = (const float*)d_in[9];
    const float* wo   = (const float*)d_in[10];
    const float* bo   = (const float*)d_in[11];
    const float* w1   = (const float*)d_in[12];
    const float* b1   = (const float*)d_in[13];
    const float* w2   = (const float*)d_in[14];
    const float* b2   = (const float*)d_in[15];
    const float* g1   = (const float*)d_in[16];
    const float* be1  = (const float*)d_in[17];
    const float* g2   = (const float*)d_in[18];
    const float* be2  = (const float*)d_in[19];
    const float* wout = (const float*)d_in[20];
    const float* bout = (const float*)d_in[21];
    float* out = (float*)d_out;

    static float *p_h=nullptr,*p_ht,*p_qkv,*p_ot,*p_p,*p_fft,*p_wt,*p_b3;
    if (!p_h) {
        void* p;
        cudaGetSymbolAddress(&p, g_h);   p_h   = (float*)p;
        cudaGetSymbolAddress(&p, g_ht);  p_ht  = (float*)p;
        cudaGetSymbolAddress(&p, g_qkv); p_qkv = (float*)p;
        cudaGetSymbolAddress(&p, g_ot);  p_ot  = (float*)p;
        cudaGetSymbolAddress(&p, g_p);   p_p   = (float*)p;
        cudaGetSymbolAddress(&p, g_fft); p_fft = (float*)p;
        cudaGetSymbolAddress(&p, g_wt);  p_wt  = (float*)p;
        cudaGetSymbolAddress(&p, g_b3);  p_b3  = (float*)p;
        cudaFuncSetAttribute(gemm_tf32_kernel,
            cudaFuncAttributeMaxDynamicSharedMemorySize, GEMM_SMEM);
        cudaFuncSetAttribute(attn_scores_gemm,
            cudaFuncAttributeMaxDynamicSharedMemorySize, SCORES_SMEM);
        cudaFuncSetAttribute(attn_o_mma_kernel,
            cudaFuncAttributeMaxDynamicSharedMemorySize, ATTN_SMEM);
    }

    embed_kernel<<<(MM*DD + 255)/256, 256>>>(x, emb, pe);

    const int wblk = (DD*DD/4 + 255)/256;

    for (int l = 0; l < LL; l++) {
        const float* wq_l = wq + (size_t)l*DD*DD;
        const float* wk_l = wk + (size_t)l*DD*DD;
        const float* wv_l = wv + (size_t)l*DD*DD;
        const float* wo_l = wo + (size_t)l*DD*DD;
        const float* w1_l = w1 + (size_t)l*DD*DFF;
        const float* w2_l = w2 + (size_t)l*DFF*DD;

        // ---- fused QKV ----
        cvt_tf32_cols_kernel<<<wblk, 256>>>(wq_l, p_wt, DD, DD, QSTR, 0);
        cvt_tf32_cols_kernel<<<wblk, 256>>>(wk_l, p_wt, DD, DD, QSTR, DD);
        cvt_tf32_cols_kernel<<<wblk, 256>>>(wv_l, p_wt, DD, DD, QSTR, 2*DD);
        concat3_kernel<<<(QSTR+255)/256, 256>>>(bq + l*DD, bk + l*DD, bv + l*DD, p_b3);
        dim3 gqkv(MM/128, QSTR/256);
        gemm_tf32_kernel<<<gqkv, 512, GEMM_SMEM>>>(p_ht, p_wt, p_b3, p_qkv, DD, QSTR, 2);

        // ---- attention ----
        float* amap_l = out + LOGITS_ELEMS + (size_t)l*AMAP_ELEMS;
        dim3 gsc(36, BB*HH);
        attn_scores_gemm<<<gsc, 256, SCORES_SMEM>>>(p_qkv, amap_l);
        dim3 gsm(SS, BB*HH);
        softmax_rows<<<gsm, 256>>>(amap_l);
        dim3 gao(SS/128, BB*HH);
        attn_o_mma_kernel<<<gao, 256, ATTN_SMEM>>>(amap_l, p_qkv, p_ot);

        // ---- output projection ----
        cvtw(wo_l, p_wt, (size_t)DD*DD);
        dim3 gproj(MM/128, DD/256);
        gemm_tf32_kernel<<<gproj, 512, GEMM_SMEM>>>(p_ot, p_wt, bo + l*DD, p_p, DD, DD, 0);
        add_ln_kernel<<<MM, 256>>>(p_h, p_p, g1 + l*DD, be1 + l*DD, p_h, p_ht);

        // ---- FFN ----
        cvtw(w1_l, p_wt, (size_t)DD*DFF);
        dim3 gff1(MM/128, DFF/256);
        gemm_tf32_kernel<<<gff1, 512, GEMM_SMEM>>>(p_ht, p_wt, b1 + l*DFF, p_fft, DD, DFF, 3);

        cvtw(w2_l, p_wt, (size_t)DFF*DD);
        dim3 gff2(MM/128, DD/256);
        gemm_tf32_kernel<<<gff2, 512, GEMM_SMEM>>>(p_fft, p_wt, b2 + l*DD, p_p, DFF, DD, 0);
        add_ln_kernel<<<MM, 256>>>(p_h, p_p, g2 + l*DD, be2 + l*DD, p_h, p_ht);
    }

    // ---- logits ----
    cvtw(wout, p_wt, (size_t)DD*VV);
    dim3 glog(MM/128, VV/256);
    gemm_tf32_kernel<<<glog, 512, GEMM_SMEM>>>(p_ht, p_wt, bout, out, DD, VV, 0);
}

// round 10
// speedup vs baseline: 1.6743x; 1.0420x over previous
#include <cuda_runtime.h>
#include <math.h>
#include <stdint.h>

#define BB   4
#define SS   1024
#define DD   768
#define HH   12
#define VV   32000
#define LL   2
#define DK   64
#define DFF  3072
#define MM   (BB*SS)
#define QSTR (3*DD)

#define LOGITS_ELEMS ((size_t)BB*SS*VV)
#define AMAP_ELEMS   ((size_t)BB*HH*SS*SS)

// ---------------- scratch ----------------
__device__ float g_h  [MM*DD];
__device__ float g_ht [MM*DD];
__device__ float g_qkv[MM*QSTR];
__device__ float g_ot [MM*DD];
__device__ float g_p  [MM*DD];
__device__ float g_fft[MM*DFF];
__device__ float g_wt [(size_t)DD*VV];
__device__ float g_b3 [QSTR];

__device__ __forceinline__ uint32_t f2tf32(float x) {
    uint32_t r;
    asm("cvt.rna.tf32.f32 %0, %1;" : "=r"(r) : "f"(x));
    return r;
}
__device__ __forceinline__ float tf32r(float x) {
    return __uint_as_float(f2tf32(x));
}
__device__ __forceinline__ void cp_async16(void* sdst, const void* gsrc) {
    uint32_t s = (uint32_t)__cvta_generic_to_shared(sdst);
    asm volatile("cp.async.cg.shared.global [%0], [%1], 16;" :: "r"(s), "l"(gsrc));
}
#define CP_COMMIT() asm volatile("cp.async.commit_group;")
#define CP_WAIT(n)  asm volatile("cp.async.wait_group %0;" :: "n"(n))

#define LDSM4(R0,R1,R2,R3,ADDR) \
    asm volatile("ldmatrix.sync.aligned.m8n8.x4.shared.b16 {%0,%1,%2,%3}, [%4];" \
        : "=r"(R0), "=r"(R1), "=r"(R2), "=r"(R3) : "r"(ADDR))

#define MMA_TF32(ACC, AF, B0, B1) \
    asm volatile("mma.sync.aligned.m16n8k8.row.col.f32.tf32.tf32.f32 " \
        "{%0,%1,%2,%3}, {%4,%5,%6,%7}, {%8,%9}, {%0,%1,%2,%3};" \
        : "+f"((ACC)[0]), "+f"((ACC)[1]), "+f"((ACC)[2]), "+f"((ACC)[3]) \
        : "r"((AF)[0]), "r"((AF)[1]), "r"((AF)[2]), "r"((AF)[3]), \
          "r"(B0), "r"(B1))

// ---------------- weight rounding ----------------
__global__ void cvt_tf32_kernel(const float4* __restrict__ src,
                                float4* __restrict__ dst, int n4)
{
    int i = blockIdx.x * 256 + threadIdx.x;
    if (i >= n4) return;
    float4 v = src[i];
    v.x = tf32r(v.x); v.y = tf32r(v.y); v.z = tf32r(v.z); v.w = tf32r(v.w);
    dst[i] = v;
}
__global__ void cvt_tf32_cols_kernel(const float* __restrict__ src,
                                     float* __restrict__ dst,
                                     int rows, int cols, int dstr, int coff)
{
    int i = blockIdx.x * 256 + threadIdx.x;
    int c4 = cols >> 2;
    if (i >= rows * c4) return;
    int r = i / c4;
    int c = (i - r*c4) << 2;
    float4 v = *(const float4*)(src + (size_t)r*cols + c);
    v.x = tf32r(v.x); v.y = tf32r(v.y); v.z = tf32r(v.z); v.w = tf32r(v.w);
    *(float4*)(dst + (size_t)r*dstr + coff + c) = v;
}
__global__ void concat3_kernel(const float* __restrict__ a,
                               const float* __restrict__ b,
                               const float* __restrict__ c,
                               float* __restrict__ dst)
{
    int i = blockIdx.x * 256 + threadIdx.x;
    if (i >= QSTR) return;
    dst[i] = (i < DD) ? a[i] : (i < 2*DD ? b[i-DD] : c[i-2*DD]);
}

// ---------------- embedding ----------------
__global__ void embed_kernel(const int* __restrict__ x,
                             const float* __restrict__ emb,
                             const float* __restrict__ pe)
{
    int i = blockIdx.x * 256 + threadIdx.x;
    if (i >= MM*DD) return;
    int row = i / DD;
    int d   = i - row*DD;
    int s   = row & (SS-1);
    int tok = x[row];
    float v = emb[(size_t)tok*DD + d] * 27.712812921102035f + pe[(size_t)s*DD + d];
    g_h[i]  = v;
    g_ht[i] = tf32r(v);
}

// ============ TF32 GEMM: BM=128 BN=256 BK=32, 512 threads, 4-stage ========
// C[M,N] = A[M,K] @ W[K,N] + bias. N must be %256. mode: bit0 relu, bit1 round.
#define A_STR 36
#define B_STR 264
#define A_TILE_F (128*A_STR)
#define B_TILE_F (32*B_STR)
#define GEMM_SMEM (4*(A_TILE_F + B_TILE_F)*4)

__global__ __launch_bounds__(512, 1)
void gemm_tf32_kernel(const float* __restrict__ A,
                      const float* __restrict__ W,
                      const float* __restrict__ bias,
                      float* __restrict__ C,
                      int K, int N, int mode)
{
    extern __shared__ float smem[];
    float* As = smem;
    float* Bs = smem + 4*A_TILE_F;

    const int tid    = threadIdx.x;
    const int wid    = tid >> 5;
    const int lane   = tid & 31;
    const int gr     = lane >> 2;
    const int ctg    = lane & 3;
    const int warp_m = wid >> 3;   // 0..1 -> 64 rows
    const int warp_n = wid & 7;    // 0..7 -> 32 cols

    const int row0 = blockIdx.x * 128;
    const int col0 = blockIdx.y * 256;

    const int a_m  = tid >> 2;
    const int a_kq = (tid & 3) * 8;
    const int b_k  = tid >> 4;
    const int b_nq = (tid & 15) * 16;

    const float* a_src = A + (size_t)(row0 + a_m)*K + a_kq;
    const float* b_src = W + (size_t)b_k*N + col0 + b_nq;

    const int row_a = ((lane >> 3) & 1) * 8 + (lane & 7);
    const int col_a = (lane >> 4) * 4;

    const uint32_t as_base = (uint32_t)__cvta_generic_to_shared(As);

    float acc[4][4][4] = {};
    const int ntiles = K >> 5;

#define G_ISSUE(tile, slot) do { \
    const float* ag = a_src + (tile)*32; \
    float* ad = &As[(slot)*A_TILE_F + a_m*A_STR + a_kq]; \
    cp_async16(ad,   ag);   cp_async16(ad+4, ag+4); \
    const float* bg = b_src + (size_t)(tile)*32*N; \
    float* bd = &Bs[(slot)*B_TILE_F + b_k*B_STR + b_nq]; \
    cp_async16(bd,    bg);    cp_async16(bd+4,  bg+4); \
    cp_async16(bd+8,  bg+8);  cp_async16(bd+12, bg+12); \
} while (0)

    G_ISSUE(0, 0); CP_COMMIT();
    G_ISSUE(1, 1); CP_COMMIT();
    G_ISSUE(2, 2); CP_COMMIT();

    for (int t = 0; t < ntiles; t++) {
        const int s = t & 3;
        CP_WAIT(2);
        __syncthreads();
        {
            const int tn = t + 3;
            if (tn < ntiles) G_ISSUE(tn, tn & 3);
            CP_COMMIT();
        }

        #pragma unroll
        for (int kk = 0; kk < 32; kk += 8) {
            uint32_t af[4][4];
            #pragma unroll
            for (int mt = 0; mt < 4; mt++) {
                uint32_t addr = as_base + 4u*((uint32_t)(s*A_TILE_F)
                              + (uint32_t)((warp_m*64 + mt*16 + row_a)*A_STR)
                              + (uint32_t)(col_a + kk));
                LDSM4(af[mt][0], af[mt][1], af[mt][2], af[mt][3], addr);
            }
            uint32_t bf[4][2];
            #pragma unroll
            for (int nt = 0; nt < 4; nt++) {
                const float* bp = &Bs[s*B_TILE_F + (kk+ctg)*B_STR + warp_n*32 + nt*8 + gr];
                bf[nt][0] = __float_as_uint(bp[0]);
                bf[nt][1] = __float_as_uint(bp[4*B_STR]);
            }
            #pragma unroll
            for (int mt = 0; mt < 4; mt++)
                #pragma unroll
                for (int nt = 0; nt < 4; nt++)
                    MMA_TF32(acc[mt][nt], af[mt], bf[nt][0], bf[nt][1]);
        }
    }
#undef G_ISSUE

    #pragma unroll
    for (int mt = 0; mt < 4; mt++) {
        int r_base = row0 + warp_m*64 + mt*16 + gr;
        #pragma unroll
        for (int nt = 0; nt < 4; nt++) {
            int c_base = col0 + warp_n*32 + nt*8 + 2*ctg;
            float b0 = bias[c_base], b1 = bias[c_base+1];
            float v0 = acc[mt][nt][0] + b0;
            float v1 = acc[mt][nt][1] + b1;
            float v2 = acc[mt][nt][2] + b0;
            float v3 = acc[mt][nt][3] + b1;
            if (mode & 1) {
                v0 = fmaxf(v0, 0.f); v1 = fmaxf(v1, 0.f);
                v2 = fmaxf(v2, 0.f); v3 = fmaxf(v3, 0.f);
            }
            if (mode & 2) {
                v0 = tf32r(v0); v1 = tf32r(v1);
                v2 = tf32r(v2); v3 = tf32r(v3);
            }
            *(float2*)(C + (size_t)r_base*N + c_base)     = make_float2(v0, v1);
            *(float2*)(C + (size_t)(r_base+8)*N + c_base) = make_float2(v2, v3);
        }
    }
}

// ============ attention scores: S = Q @ K^T ===============================
#define S_STR 68
#define SCORES_SMEM (2*128*S_STR*4)

__global__ __launch_bounds__(256)
void attn_scores_gemm(const float* __restrict__ qkv,
                      float* __restrict__ amap)
{
    extern __shared__ float smem[];
    float* As = smem;
    float* Bs = smem + 128*S_STR;

    const int tid    = threadIdx.x;
    const int wid    = tid >> 5;
    const int lane   = tid & 31;
    const int gr     = lane >> 2;
    const int ctg    = lane & 3;
    const int warp_m = wid >> 2;
    const int warp_n = wid & 3;

    int idx = blockIdx.x;
    int qb = 0;
    while ((qb+1)*(qb+2)/2 <= idx) qb++;
    int kb = idx - qb*(qb+1)/2;

    const int bh = blockIdx.y;
    const int b  = bh / HH;
    const int hh = bh - b*HH;

    const int row0 = qb * 128;
    const int col0 = kb * 128;

    const float* Qb = qkv + (size_t)(b*SS)*QSTR + hh*DK;
    const float* Kb = Qb + DD;

    const int l_m  = tid >> 1;
    const int l_kq = (tid & 1) * 32;

    {
        const float* ag = Qb + (size_t)(row0 + l_m)*QSTR + l_kq;
        float* ad = &As[l_m*S_STR + l_kq];
        #pragma unroll
        for (int i = 0; i < 8; i++) cp_async16(ad + 4*i, ag + 4*i);
        const float* bg = Kb + (size_t)(col0 + l_m)*QSTR + l_kq;
        float* bd = &Bs[l_m*S_STR + l_kq];
        #pragma unroll
        for (int i = 0; i < 8; i++) cp_async16(bd + 4*i, bg + 4*i);
    }
    CP_COMMIT();
    CP_WAIT(0);
    __syncthreads();

    const int row_a = ((lane >> 3) & 1) * 8 + (lane & 7);
    const int col_a = (lane >> 4) * 4;
    const uint32_t as_base = (uint32_t)__cvta_generic_to_shared(As);
    const uint32_t bs_base = (uint32_t)__cvta_generic_to_shared(Bs);

    float acc[4][4][4] = {};

    #pragma unroll
    for (int kk = 0; kk < 64; kk += 8) {
        uint32_t af[4][4];
        #pragma unroll
        for (int mt = 0; mt < 4; mt++) {
            uint32_t addr = as_base + 4u*(uint32_t)((warp_m*64 + mt*16 + row_a)*S_STR + col_a + kk);
            LDSM4(af[mt][0], af[mt][1], af[mt][2], af[mt][3], addr);
        }
        uint32_t bf[4][2];
        #pragma unroll
        for (int p = 0; p < 2; p++) {
            uint32_t addr = bs_base + 4u*(uint32_t)((warp_n*32 + p*16 + row_a)*S_STR + col_a + kk);
            uint32_t r0, r1, r2, r3;
            LDSM4(r0, r1, r2, r3, addr);
            bf[2*p  ][0] = r0;
            bf[2*p+1][0] = r1;
            bf[2*p  ][1] = r2;
            bf[2*p+1][1] = r3;
        }
        #pragma unroll
        for (int mt = 0; mt < 4; mt++)
            #pragma unroll
            for (int nt = 0; nt < 4; nt++)
                MMA_TF32(acc[mt][nt], af[mt], bf[nt][0], bf[nt][1]);
    }

    float* Sb = amap + (size_t)bh*SS*SS;
    #pragma unroll
    for (int mt = 0; mt < 4; mt++) {
        int r = row0 + warp_m*64 + mt*16 + gr;
        #pragma unroll
        for (int nt = 0; nt < 4; nt++) {
            int c = col0 + warp_n*32 + nt*8 + 2*ctg;
            *(float2*)(Sb + (size_t)r*SS + c) =
                make_float2(acc[mt][nt][0]*0.125f, acc[mt][nt][1]*0.125f);
            *(float2*)(Sb + (size_t)(r+8)*SS + c) =
                make_float2(acc[mt][nt][2]*0.125f, acc[mt][nt][3]*0.125f);
        }
    }
}

// ============ softmax rows, in place, float4 I/O ==========================
__global__ void softmax_rows(float* __restrict__ amap)
{
    const int qpos = blockIdx.x;
    const int bh   = blockIdx.y;
    const int tid  = threadIdx.x;
    const int wid  = tid >> 5;
    const int lane = tid & 31;

    float* row = amap + ((size_t)bh*SS + qpos)*SS;

    __shared__ float sc[SS];
    __shared__ float red[8];
    __shared__ float bcast;

    const int n4 = (qpos >> 2) + 1;   // float4 chunks covering 0..qpos

    float m = -1e30f;
    for (int i4 = tid; i4 < n4; i4 += 256) {
        float4 v = ((const float4*)row)[i4];
        int k = i4 << 2;
        sc[k]   = v.x;
        sc[k+1] = v.y;
        sc[k+2] = v.z;
        sc[k+3] = v.w;
        if (k   <= qpos) m = fmaxf(m, v.x);
        if (k+1 <= qpos) m = fmaxf(m, v.y);
        if (k+2 <= qpos) m = fmaxf(m, v.z);
        if (k+3 <= qpos) m = fmaxf(m, v.w);
    }
    #pragma unroll
    for (int o = 16; o > 0; o >>= 1) m = fmaxf(m, __shfl_xor_sync(0xffffffffu, m, o));
    if (lane == 0) red[wid] = m;
    __syncthreads();
    if (tid == 0) {
        float mm = red[0];
        #pragma unroll
        for (int i = 1; i < 8; i++) mm = fmaxf(mm, red[i]);
        bcast = mm;
    }
    __syncthreads();
    m = bcast;

    float s = 0.0f;
    for (int k = tid; k <= qpos; k += 256) {
        float e = __expf(sc[k] - m);
        sc[k] = e;
        s += e;
    }
    #pragma unroll
    for (int o = 16; o > 0; o >>= 1) s += __shfl_xor_sync(0xffffffffu, s, o);
    if (lane == 0) red[wid] = s;
    __syncthreads();
    if (tid == 0) {
        float ss = red[0];
        #pragma unroll
        for (int i = 1; i < 8; i++) ss += red[i];
        bcast = 1.0f / ss;
    }
    __syncthreads();
    float inv = bcast;

    // write: exactly one float4 per thread (SS/4 = 256)
    {
        int k = tid << 2;
        float4 o;
        o.x = (k   <= qpos) ? sc[k]   * inv : 0.0f;
        o.y = (k+1 <= qpos) ? sc[k+1] * inv : 0.0f;
        o.z = (k+2 <= qpos) ? sc[k+2] * inv : 0.0f;
        o.w = (k+3 <= qpos) ? sc[k+3] * inv : 0.0f;
        ((float4*)row)[tid] = o;
    }
}

// ============ attn_o: O = amap @ V, rounded output ========================
#define AS_PAD 36
#define BO_PAD 68
#define ATTN_SMEM ((2*128*AS_PAD + 2*32*BO_PAD)*4)
__global__ __launch_bounds__(256)
void attn_o_mma_kernel(const float* __restrict__ amap,
                       const float* __restrict__ qkv,
                       float* __restrict__ O)
{
    extern __shared__ float smem[];
    float* As = smem;
    float* Bs = smem + 2*128*AS_PAD;
#define ASM(b,m,k) As[((b)*128+(m))*AS_PAD+(k)]
#define BSM(b,k,n) Bs[((b)*32+(k))*BO_PAD+(n)]

    const int tid    = threadIdx.x;
    const int wid    = tid >> 5;
    const int lane   = tid & 31;
    const int gr     = lane >> 2;
    const int ctg    = lane & 3;
    const int warp_m = wid & 3;
    const int warp_n = wid >> 2;

    const int row0 = blockIdx.x * 128;
    const int bh   = blockIdx.y;
    const int b    = bh / HH;
    const int hh   = bh - b*HH;

    const float* Arow = amap + (size_t)bh*SS*SS;
    const float* Vb   = qkv + (size_t)(b*SS)*QSTR + 2*DD + hh*DK;

    const int a_m  = tid >> 1;
    const int a_kq = (tid & 1) * 16;
    const int b_k  = tid >> 3;
    const int b_nq = (tid & 7) * 8;

    const float* a_src = Arow + (size_t)(row0 + a_m)*SS + a_kq;
    const float* b_src = Vb + (size_t)b_k*QSTR + b_nq;

    float acc[2][4][4] = {};
    const int nt = (row0 + 128) >> 5;

    #pragma unroll
    for (int i = 0; i < 4; i++) cp_async16(&ASM(0, a_m, a_kq + 4*i), a_src + 4*i);
    #pragma unroll
    for (int i = 0; i < 2; i++) cp_async16(&BSM(0, b_k, b_nq + 4*i), b_src + 4*i);
    CP_COMMIT();

    for (int t = 0; t < nt; t++) {
        const int cur = t & 1;
        if (t + 1 < nt) {
            const int nb = cur ^ 1;
            const int k0 = (t+1) << 5;
            #pragma unroll
            for (int i = 0; i < 4; i++)
                cp_async16(&ASM(nb, a_m, a_kq + 4*i), a_src + k0 + 4*i);
            #pragma unroll
            for (int i = 0; i < 2; i++)
                cp_async16(&BSM(nb, b_k, b_nq + 4*i), b_src + (size_t)k0*QSTR + 4*i);
            CP_COMMIT();
            CP_WAIT(1);
        } else {
            CP_WAIT(0);
        }
        __syncthreads();

        #pragma unroll
        for (int kk = 0; kk < 32; kk += 8) {
            uint32_t af[2][4];
            #pragma unroll
            for (int mt = 0; mt < 2; mt++) {
                int mb = warp_m*32 + mt*16;
                af[mt][0] = f2tf32(ASM(cur, mb+gr,   kk+ctg));
                af[mt][1] = f2tf32(ASM(cur, mb+gr+8, kk+ctg));
                af[mt][2] = f2tf32(ASM(cur, mb+gr,   kk+ctg+4));
                af[mt][3] = f2tf32(ASM(cur, mb+gr+8, kk+ctg+4));
            }
            uint32_t bf[4][2];
            #pragma unroll
            for (int ntl = 0; ntl < 4; ntl++) {
                int nb = warp_n*32 + ntl*8;
                bf[ntl][0] = __float_as_uint(BSM(cur, kk+ctg,   nb+gr));
                bf[ntl][1] = __float_as_uint(BSM(cur, kk+ctg+4, nb+gr));
            }
            #pragma unroll
            for (int mt = 0; mt < 2; mt++)
                #pragma unroll
                for (int ntl = 0; ntl < 4; ntl++)
                    MMA_TF32(acc[mt][ntl], af[mt], bf[ntl][0], bf[ntl][1]);
        }
        __syncthreads();
    }

    #pragma unroll
    for (int mt = 0; mt < 2; mt++) {
        int r = row0 + warp_m*32 + mt*16 + gr;
        #pragma unroll
        for (int ntl = 0; ntl < 4; ntl++) {
            int c = warp_n*32 + ntl*8 + 2*ctg;
            float* dst = O + (size_t)(b*SS + r)*DD + hh*DK + c;
            *(float2*)dst = make_float2(tf32r(acc[mt][ntl][0]), tf32r(acc[mt][ntl][1]));
            *(float2*)(dst + 8*DD) = make_float2(tf32r(acc[mt][ntl][2]), tf32r(acc[mt][ntl][3]));
        }
    }
#undef ASM
#undef BSM
}

// ---------------- residual add + layernorm --------------------------------
__global__ void add_ln_kernel(const float* __restrict__ res,
                              const float* __restrict__ x,
                              const float* __restrict__ g,
                              const float* __restrict__ be,
                              float* __restrict__ out,
                              float* __restrict__ outt)
{
    const int row = blockIdx.x;
    const int tid = threadIdx.x;
    __shared__ float buf[DD];
    __shared__ float red[256];

    float s = 0.0f;
    for (int d = tid; d < DD; d += 256) {
        float v = res[(size_t)row*DD + d] + x[(size_t)row*DD + d];
        buf[d] = v;
        s += v;
    }
    red[tid] = s; __syncthreads();
    for (int t = 128; t > 0; t >>= 1) {
        if (tid < t) red[tid] += red[tid+t];
        __syncthreads();
    }
    float mean = red[0] * (1.0f/DD);
    __syncthreads();

    float vs = 0.0f;
    for (int d = tid; d < DD; d += 256) {
        float dv = buf[d] - mean;
        vs += dv*dv;
    }
    red[tid] = vs; __syncthreads();
    for (int t = 128; t > 0; t >>= 1) {
        if (tid < t) red[tid] += red[tid+t];
        __syncthreads();
    }
    float rstd = rsqrtf(red[0] * (1.0f/DD) + 1e-5f);

    for (int d = tid; d < DD; d += 256) {
        float v = (buf[d] - mean)*rstd*g[d] + be[d];
        out [(size_t)row*DD + d] = v;
        outt[(size_t)row*DD + d] = tf32r(v);
    }
}

// ---------------------------------------------------------------------------
static inline void cvtw(const float* src, float* dst, size_t n) {
    int n4 = (int)(n >> 2);
    cvt_tf32_kernel<<<(n4 + 255)/256, 256>>>((const float4*)src, (float4*)dst, n4);
}

extern "C" void kernel_launch(void* const* d_in, const int* in_sizes, int n_in,
                              void* d_out, int out_size)
{
    (void)in_sizes; (void)n_in; (void)out_size;

    const int*   x    = (const int*)  d_in[0];
    const float* emb  = (const float*)d_in[2];
    const float* pe   = (const float*)d_in[3];
    const float* wq   = (const float*)d_in[4];
    const float* bq   = (const float*)d_in[5];
    const float* wk   = (const float*)d_in[6];
    const float* bk   = (const float*)d_in[7];
    const float* wv   = (const float*)d_in[8];
    const float* bv   = (const float*)d_in[9];
    const float* wo   = (const float*)d_in[10];
    const float* bo   = (const float*)d_in[11];
    const float* w1   = (const float*)d_in[12];
    const float* b1   = (const float*)d_in[13];
    const float* w2   = (const float*)d_in[14];
    const float* b2   = (const float*)d_in[15];
    const float* g1   = (const float*)d_in[16];
    const float* be1  = (const float*)d_in[17];
    const float* g2   = (const float*)d_in[18];
    const float* be2  = (const float*)d_in[19];
    const float* wout = (const float*)d_in[20];
    const float* bout = (const float*)d_in[21];
    float* out = (float*)d_out;

    static float *p_h=nullptr,*p_ht,*p_qkv,*p_ot,*p_p,*p_fft,*p_wt,*p_b3;
    if (!p_h) {
        void* p;
        cudaGetSymbolAddress(&p, g_h);   p_h   = (float*)p;
        cudaGetSymbolAddress(&p, g_ht);  p_ht  = (float*)p;
        cudaGetSymbolAddress(&p, g_qkv); p_qkv = (float*)p;
        cudaGetSymbolAddress(&p, g_ot);  p_ot  = (float*)p;
        cudaGetSymbolAddress(&p, g_p);   p_p   = (float*)p;
        cudaGetSymbolAddress(&p, g_fft); p_fft = (float*)p;
        cudaGetSymbolAddress(&p, g_wt);  p_wt  = (float*)p;
        cudaGetSymbolAddress(&p, g_b3);  p_b3  = (float*)p;
        cudaFuncSetAttribute(gemm_tf32_kernel,
            cudaFuncAttributeMaxDynamicSharedMemorySize, GEMM_SMEM);
        cudaFuncSetAttribute(attn_scores_gemm,
            cudaFuncAttributeMaxDynamicSharedMemorySize, SCORES_SMEM);
        cudaFuncSetAttribute(attn_o_mma_kernel,
            cudaFuncAttributeMaxDynamicSharedMemorySize, ATTN_SMEM);
    }

    embed_kernel<<<(MM*DD + 255)/256, 256>>>(x, emb, pe);

    const int wblk = (DD*DD/4 + 255)/256;

    for (int l = 0; l < LL; l++) {
        const float* wq_l = wq + (size_t)l*DD*DD;
        const float* wk_l = wk + (size_t)l*DD*DD;
        const float* wv_l = wv + (size_t)l*DD*DD;
        const float* wo_l = wo + (size_t)l*DD*DD;
        const float* w1_l = w1 + (size_t)l*DD*DFF;
        const float* w2_l = w2 + (size_t)l*DFF*DD;

        // ---- fused QKV ----
        cvt_tf32_cols_kernel<<<wblk, 256>>>(wq_l, p_wt, DD, DD, QSTR, 0);
        cvt_tf32_cols_kernel<<<wblk, 256>>>(wk_l, p_wt, DD, DD, QSTR, DD);
        cvt_tf32_cols_kernel<<<wblk, 256>>>(wv_l, p_wt, DD, DD, QSTR, 2*DD);
        concat3_kernel<<<(QSTR+255)/256, 256>>>(bq + l*DD, bk + l*DD, bv + l*DD, p_b3);
        dim3 gqkv(MM/128, QSTR/256);
        gemm_tf32_kernel<<<gqkv, 512, GEMM_SMEM>>>(p_ht, p_wt, p_b3, p_qkv, DD, QSTR, 2);

        // ---- attention ----
        float* amap_l = out + LOGITS_ELEMS + (size_t)l*AMAP_ELEMS;
        dim3 gsc(36, BB*HH);
        attn_scores_gemm<<<gsc, 256, SCORES_SMEM>>>(p_qkv, amap_l);
        dim3 gsm(SS, BB*HH);
        softmax_rows<<<gsm, 256>>>(amap_l);
        dim3 gao(SS/128, BB*HH);
        attn_o_mma_kernel<<<gao, 256, ATTN_SMEM>>>(amap_l, p_qkv, p_ot);

        // ---- output projection ----
        cvtw(wo_l, p_wt, (size_t)DD*DD);
        dim3 gproj(MM/128, DD/256);
        gemm_tf32_kernel<<<gproj, 512, GEMM_SMEM>>>(p_ot, p_wt, bo + l*DD, p_p, DD, DD, 0);
        add_ln_kernel<<<MM, 256>>>(p_h, p_p, g1 + l*DD, be1 + l*DD, p_h, p_ht);

        // ---- FFN ----
        cvtw(w1_l, p_wt, (size_t)DD*DFF);
        dim3 gff1(MM/128, DFF/256);
        gemm_tf32_kernel<<<gff1, 512, GEMM_SMEM>>>(p_ht, p_wt, b1 + l*DFF, p_fft, DD, DFF, 3);

        cvtw(w2_l, p_wt, (size_t)DFF*DD);
        dim3 gff2(MM/128, DD/256);
        gemm_tf32_kernel<<<gff2, 512, GEMM_SMEM>>>(p_fft, p_wt, b2 + l*DD, p_p, DFF, DD, 0);
        add_ln_kernel<<<MM, 256>>>(p_h, p_p, g2 + l*DD, be2 + l*DD, p_h, p_ht);
    }

    // ---- logits ----
    cvtw(wout, p_wt, (size_t)DD*VV);
    dim3 glog(MM/128, VV/256);
    gemm_tf32_kernel<<<glog, 512, GEMM_SMEM>>>(p_ht, p_wt, bout, out, DD, VV, 0);
}

// round 11
// speedup vs baseline: 1.7160x; 1.0249x over previous
#include <cuda_runtime.h>
#include <math.h>
#include <stdint.h>

#define BB   4
#define SS   1024
#define DD   768
#define HH   12
#define VV   32000
#define LL   2
#define DK   64
#define DFF  3072
#define MM   (BB*SS)
#define QSTR (3*DD)

#define LOGITS_ELEMS ((size_t)BB*SS*VV)
#define AMAP_ELEMS   ((size_t)BB*HH*SS*SS)

// ---------------- scratch ----------------
__device__ float g_h  [MM*DD];
__device__ float g_ht [MM*DD];
__device__ float g_qkv[MM*QSTR];
__device__ float g_ot [MM*DD];
__device__ float g_p  [MM*DD];
__device__ float g_fft[MM*DFF];
// dedicated rounded-weight buffers (so cvts can run ahead on a side stream)
__device__ float g_wqkv[LL][(size_t)DD*QSTR];
__device__ float g_wo  [LL][(size_t)DD*DD];
__device__ float g_w1  [LL][(size_t)DD*DFF];
__device__ float g_w2  [LL][(size_t)DFF*DD];
__device__ float g_wout[(size_t)DD*VV];
__device__ float g_b3  [LL][QSTR];

__device__ __forceinline__ uint32_t f2tf32(float x) {
    uint32_t r;
    asm("cvt.rna.tf32.f32 %0, %1;" : "=r"(r) : "f"(x));
    return r;
}
__device__ __forceinline__ float tf32r(float x) {
    return __uint_as_float(f2tf32(x));
}
__device__ __forceinline__ void cp_async16(void* sdst, const void* gsrc) {
    uint32_t s = (uint32_t)__cvta_generic_to_shared(sdst);
    asm volatile("cp.async.cg.shared.global [%0], [%1], 16;" :: "r"(s), "l"(gsrc));
}
#define CP_COMMIT() asm volatile("cp.async.commit_group;")
#define CP_WAIT(n)  asm volatile("cp.async.wait_group %0;" :: "n"(n))

#define LDSM4(R0,R1,R2,R3,ADDR) \
    asm volatile("ldmatrix.sync.aligned.m8n8.x4.shared.b16 {%0,%1,%2,%3}, [%4];" \
        : "=r"(R0), "=r"(R1), "=r"(R2), "=r"(R3) : "r"(ADDR))

#define MMA_TF32(ACC, AF, B0, B1) \
    asm volatile("mma.sync.aligned.m16n8k8.row.col.f32.tf32.tf32.f32 " \
        "{%0,%1,%2,%3}, {%4,%5,%6,%7}, {%8,%9}, {%0,%1,%2,%3};" \
        : "+f"((ACC)[0]), "+f"((ACC)[1]), "+f"((ACC)[2]), "+f"((ACC)[3]) \
        : "r"((AF)[0]), "r"((AF)[1]), "r"((AF)[2]), "r"((AF)[3]), \
          "r"(B0), "r"(B1))

// ---------------- weight rounding ----------------
__global__ void cvt_tf32_kernel(const float4* __restrict__ src,
                                float4* __restrict__ dst, int n4)
{
    int i = blockIdx.x * 256 + threadIdx.x;
    if (i >= n4) return;
    float4 v = src[i];
    v.x = tf32r(v.x); v.y = tf32r(v.y); v.z = tf32r(v.z); v.w = tf32r(v.w);
    dst[i] = v;
}
__global__ void cvt_tf32_cols_kernel(const float* __restrict__ src,
                                     float* __restrict__ dst,
                                     int rows, int cols, int dstr, int coff)
{
    int i = blockIdx.x * 256 + threadIdx.x;
    int c4 = cols >> 2;
    if (i >= rows * c4) return;
    int r = i / c4;
    int c = (i - r*c4) << 2;
    float4 v = *(const float4*)(src + (size_t)r*cols + c);
    v.x = tf32r(v.x); v.y = tf32r(v.y); v.z = tf32r(v.z); v.w = tf32r(v.w);
    *(float4*)(dst + (size_t)r*dstr + coff + c) = v;
}
__global__ void concat3_kernel(const float* __restrict__ a,
                               const float* __restrict__ b,
                               const float* __restrict__ c,
                               float* __restrict__ dst)
{
    int i = blockIdx.x * 256 + threadIdx.x;
    if (i >= QSTR) return;
    dst[i] = (i < DD) ? a[i] : (i < 2*DD ? b[i-DD] : c[i-2*DD]);
}

// ---------------- embedding (float4) ----------------
__global__ void embed_kernel(const int* __restrict__ x,
                             const float* __restrict__ emb,
                             const float* __restrict__ pe)
{
    int i4 = blockIdx.x * 256 + threadIdx.x;
    if (i4 >= MM*DD/4) return;
    int row = i4 / (DD/4);
    int d4  = i4 - row*(DD/4);
    int s   = row & (SS-1);
    int tok = x[row];
    float4 e = ((const float4*)emb)[(size_t)tok*(DD/4) + d4];
    float4 p = ((const float4*)pe)[(size_t)s*(DD/4) + d4];
    const float sc = 27.712812921102035f;
    float4 v;
    v.x = e.x*sc + p.x; v.y = e.y*sc + p.y;
    v.z = e.z*sc + p.z; v.w = e.w*sc + p.w;
    ((float4*)g_h)[i4] = v;
    float4 t;
    t.x = tf32r(v.x); t.y = tf32r(v.y); t.z = tf32r(v.z); t.w = tf32r(v.w);
    ((float4*)g_ht)[i4] = t;
}

// ============ TF32 GEMM: BM=128 BN=256 BK=32, 512 threads, 4-stage ========
#define A_STR 36
#define B_STR 264
#define A_TILE_F (128*A_STR)
#define B_TILE_F (32*B_STR)
#define GEMM_SMEM (4*(A_TILE_F + B_TILE_F)*4)

__global__ __launch_bounds__(512, 1)
void gemm_tf32_kernel(const float* __restrict__ A,
                      const float* __restrict__ W,
                      const float* __restrict__ bias,
                      float* __restrict__ C,
                      int K, int N, int mode)
{
    extern __shared__ float smem[];
    float* As = smem;
    float* Bs = smem + 4*A_TILE_F;

    const int tid    = threadIdx.x;
    const int wid    = tid >> 5;
    const int lane   = tid & 31;
    const int gr     = lane >> 2;
    const int ctg    = lane & 3;
    const int warp_m = wid >> 3;
    const int warp_n = wid & 7;

    const int row0 = blockIdx.x * 128;
    const int col0 = blockIdx.y * 256;

    const int a_m  = tid >> 2;
    const int a_kq = (tid & 3) * 8;
    const int b_k  = tid >> 4;
    const int b_nq = (tid & 15) * 16;

    const float* a_src = A + (size_t)(row0 + a_m)*K + a_kq;
    const float* b_src = W + (size_t)b_k*N + col0 + b_nq;

    const int row_a = ((lane >> 3) & 1) * 8 + (lane & 7);
    const int col_a = (lane >> 4) * 4;

    const uint32_t as_base = (uint32_t)__cvta_generic_to_shared(As);

    float acc[4][4][4] = {};
    const int ntiles = K >> 5;

#define G_ISSUE(tile, slot) do { \
    const float* ag = a_src + (tile)*32; \
    float* ad = &As[(slot)*A_TILE_F + a_m*A_STR + a_kq]; \
    cp_async16(ad,   ag);   cp_async16(ad+4, ag+4); \
    const float* bg = b_src + (size_t)(tile)*32*N; \
    float* bd = &Bs[(slot)*B_TILE_F + b_k*B_STR + b_nq]; \
    cp_async16(bd,    bg);    cp_async16(bd+4,  bg+4); \
    cp_async16(bd+8,  bg+8);  cp_async16(bd+12, bg+12); \
} while (0)

    G_ISSUE(0, 0); CP_COMMIT();
    G_ISSUE(1, 1); CP_COMMIT();
    G_ISSUE(2, 2); CP_COMMIT();

    for (int t = 0; t < ntiles; t++) {
        const int s = t & 3;
        CP_WAIT(2);
        __syncthreads();
        {
            const int tn = t + 3;
            if (tn < ntiles) G_ISSUE(tn, tn & 3);
            CP_COMMIT();
        }

        #pragma unroll
        for (int kk = 0; kk < 32; kk += 8) {
            uint32_t af[4][4];
            #pragma unroll
            for (int mt = 0; mt < 4; mt++) {
                uint32_t addr = as_base + 4u*((uint32_t)(s*A_TILE_F)
                              + (uint32_t)((warp_m*64 + mt*16 + row_a)*A_STR)
                              + (uint32_t)(col_a + kk));
                LDSM4(af[mt][0], af[mt][1], af[mt][2], af[mt][3], addr);
            }
            uint32_t bf[4][2];
            #pragma unroll
            for (int nt = 0; nt < 4; nt++) {
                const float* bp = &Bs[s*B_TILE_F + (kk+ctg)*B_STR + warp_n*32 + nt*8 + gr];
                bf[nt][0] = __float_as_uint(bp[0]);
                bf[nt][1] = __float_as_uint(bp[4*B_STR]);
            }
            #pragma unroll
            for (int mt = 0; mt < 4; mt++)
                #pragma unroll
                for (int nt = 0; nt < 4; nt++)
                    MMA_TF32(acc[mt][nt], af[mt], bf[nt][0], bf[nt][1]);
        }
    }
#undef G_ISSUE

    #pragma unroll
    for (int mt = 0; mt < 4; mt++) {
        int r_base = row0 + warp_m*64 + mt*16 + gr;
        #pragma unroll
        for (int nt = 0; nt < 4; nt++) {
            int c_base = col0 + warp_n*32 + nt*8 + 2*ctg;
            float b0 = bias[c_base], b1 = bias[c_base+1];
            float v0 = acc[mt][nt][0] + b0;
            float v1 = acc[mt][nt][1] + b1;
            float v2 = acc[mt][nt][2] + b0;
            float v3 = acc[mt][nt][3] + b1;
            if (mode & 1) {
                v0 = fmaxf(v0, 0.f); v1 = fmaxf(v1, 0.f);
                v2 = fmaxf(v2, 0.f); v3 = fmaxf(v3, 0.f);
            }
            if (mode & 2) {
                v0 = tf32r(v0); v1 = tf32r(v1);
                v2 = tf32r(v2); v3 = tf32r(v3);
            }
            *(float2*)(C + (size_t)r_base*N + c_base)     = make_float2(v0, v1);
            *(float2*)(C + (size_t)(r_base+8)*N + c_base) = make_float2(v2, v3);
        }
    }
}

// ============ attention scores: S = Q @ K^T ===============================
#define S_STR 68
#define SCORES_SMEM (2*128*S_STR*4)

__global__ __launch_bounds__(256)
void attn_scores_gemm(const float* __restrict__ qkv,
                      float* __restrict__ amap)
{
    extern __shared__ float smem[];
    float* As = smem;
    float* Bs = smem + 128*S_STR;

    const int tid    = threadIdx.x;
    const int wid    = tid >> 5;
    const int lane   = tid & 31;
    const int gr     = lane >> 2;
    const int ctg    = lane & 3;
    const int warp_m = wid >> 2;
    const int warp_n = wid & 3;

    int idx = blockIdx.x;
    int qb = 0;
    while ((qb+1)*(qb+2)/2 <= idx) qb++;
    int kb = idx - qb*(qb+1)/2;

    const int bh = blockIdx.y;
    const int b  = bh / HH;
    const int hh = bh - b*HH;

    const int row0 = qb * 128;
    const int col0 = kb * 128;

    const float* Qb = qkv + (size_t)(b*SS)*QSTR + hh*DK;
    const float* Kb = Qb + DD;

    const int l_m  = tid >> 1;
    const int l_kq = (tid & 1) * 32;

    {
        const float* ag = Qb + (size_t)(row0 + l_m)*QSTR + l_kq;
        float* ad = &As[l_m*S_STR + l_kq];
        #pragma unroll
        for (int i = 0; i < 8; i++) cp_async16(ad + 4*i, ag + 4*i);
        const float* bg = Kb + (size_t)(col0 + l_m)*QSTR + l_kq;
        float* bd = &Bs[l_m*S_STR + l_kq];
        #pragma unroll
        for (int i = 0; i < 8; i++) cp_async16(bd + 4*i, bg + 4*i);
    }
    CP_COMMIT();
    CP_WAIT(0);
    __syncthreads();

    const int row_a = ((lane >> 3) & 1) * 8 + (lane & 7);
    const int col_a = (lane >> 4) * 4;
    const uint32_t as_base = (uint32_t)__cvta_generic_to_shared(As);
    const uint32_t bs_base = (uint32_t)__cvta_generic_to_shared(Bs);

    float acc[4][4][4] = {};

    #pragma unroll
    for (int kk = 0; kk < 64; kk += 8) {
        uint32_t af[4][4];
        #pragma unroll
        for (int mt = 0; mt < 4; mt++) {
            uint32_t addr = as_base + 4u*(uint32_t)((warp_m*64 + mt*16 + row_a)*S_STR + col_a + kk);
            LDSM4(af[mt][0], af[mt][1], af[mt][2], af[mt][3], addr);
        }
        uint32_t bf[4][2];
        #pragma unroll
        for (int p = 0; p < 2; p++) {
            uint32_t addr = bs_base + 4u*(uint32_t)((warp_n*32 + p*16 + row_a)*S_STR + col_a + kk);
            uint32_t r0, r1, r2, r3;
            LDSM4(r0, r1, r2, r3, addr);
            bf[2*p  ][0] = r0;
            bf[2*p+1][0] = r1;
            bf[2*p  ][1] = r2;
            bf[2*p+1][1] = r3;
        }
        #pragma unroll
        for (int mt = 0; mt < 4; mt++)
            #pragma unroll
            for (int nt = 0; nt < 4; nt++)
                MMA_TF32(acc[mt][nt], af[mt], bf[nt][0], bf[nt][1]);
    }

    float* Sb = amap + (size_t)bh*SS*SS;
    #pragma unroll
    for (int mt = 0; mt < 4; mt++) {
        int r = row0 + warp_m*64 + mt*16 + gr;
        #pragma unroll
        for (int nt = 0; nt < 4; nt++) {
            int c = col0 + warp_n*32 + nt*8 + 2*ctg;
            *(float2*)(Sb + (size_t)r*SS + c) =
                make_float2(acc[mt][nt][0]*0.125f, acc[mt][nt][1]*0.125f);
            *(float2*)(Sb + (size_t)(r+8)*SS + c) =
                make_float2(acc[mt][nt][2]*0.125f, acc[mt][nt][3]*0.125f);
        }
    }
}

// ============ softmax rows, in place, float4 I/O ==========================
__global__ void softmax_rows(float* __restrict__ amap)
{
    const int qpos = blockIdx.x;
    const int bh   = blockIdx.y;
    const int tid  = threadIdx.x;
    const int wid  = tid >> 5;
    const int lane = tid & 31;

    float* row = amap + ((size_t)bh*SS + qpos)*SS;

    __shared__ float sc[SS];
    __shared__ float red[8];
    __shared__ float bcast;

    const int n4 = (qpos >> 2) + 1;

    float m = -1e30f;
    for (int i4 = tid; i4 < n4; i4 += 256) {
        float4 v = ((const float4*)row)[i4];
        int k = i4 << 2;
        sc[k]   = v.x;
        sc[k+1] = v.y;
        sc[k+2] = v.z;
        sc[k+3] = v.w;
        if (k   <= qpos) m = fmaxf(m, v.x);
        if (k+1 <= qpos) m = fmaxf(m, v.y);
        if (k+2 <= qpos) m = fmaxf(m, v.z);
        if (k+3 <= qpos) m = fmaxf(m, v.w);
    }
    #pragma unroll
    for (int o = 16; o > 0; o >>= 1) m = fmaxf(m, __shfl_xor_sync(0xffffffffu, m, o));
    if (lane == 0) red[wid] = m;
    __syncthreads();
    if (tid == 0) {
        float mm = red[0];
        #pragma unroll
        for (int i = 1; i < 8; i++) mm = fmaxf(mm, red[i]);
        bcast = mm;
    }
    __syncthreads();
    m = bcast;

    float s = 0.0f;
    for (int k = tid; k <= qpos; k += 256) {
        float e = __expf(sc[k] - m);
        sc[k] = e;
        s += e;
    }
    #pragma unroll
    for (int o = 16; o > 0; o >>= 1) s += __shfl_xor_sync(0xffffffffu, s, o);
    if (lane == 0) red[wid] = s;
    __syncthreads();
    if (tid == 0) {
        float ss = red[0];
        #pragma unroll
        for (int i = 1; i < 8; i++) ss += red[i];
        bcast = 1.0f / ss;
    }
    __syncthreads();
    float inv = bcast;

    {
        int k = tid << 2;
        float4 o;
        o.x = (k   <= qpos) ? sc[k]   * inv : 0.0f;
        o.y = (k+1 <= qpos) ? sc[k+1] * inv : 0.0f;
        o.z = (k+2 <= qpos) ? sc[k+2] * inv : 0.0f;
        o.w = (k+3 <= qpos) ? sc[k+3] * inv : 0.0f;
        ((float4*)row)[tid] = o;
    }
}

// ============ attn_o: O = amap @ V, rounded output ========================
#define AS_PAD 36
#define BO_PAD 68
#define ATTN_SMEM ((2*128*AS_PAD + 2*32*BO_PAD)*4)
__global__ __launch_bounds__(256)
void attn_o_mma_kernel(const float* __restrict__ amap,
                       const float* __restrict__ qkv,
                       float* __restrict__ O)
{
    extern __shared__ float smem[];
    float* As = smem;
    float* Bs = smem + 2*128*AS_PAD;
#define ASM(b,m,k) As[((b)*128+(m))*AS_PAD+(k)]
#define BSM(b,k,n) Bs[((b)*32+(k))*BO_PAD+(n)]

    const int tid    = threadIdx.x;
    const int wid    = tid >> 5;
    const int lane   = tid & 31;
    const int gr     = lane >> 2;
    const int ctg    = lane & 3;
    const int warp_m = wid & 3;
    const int warp_n = wid >> 2;

    const int row0 = blockIdx.x * 128;
    const int bh   = blockIdx.y;
    const int b    = bh / HH;
    const int hh   = bh - b*HH;

    const float* Arow = amap + (size_t)bh*SS*SS;
    const float* Vb   = qkv + (size_t)(b*SS)*QSTR + 2*DD + hh*DK;

    const int a_m  = tid >> 1;
    const int a_kq = (tid & 1) * 16;
    const int b_k  = tid >> 3;
    const int b_nq = (tid & 7) * 8;

    const float* a_src = Arow + (size_t)(row0 + a_m)*SS + a_kq;
    const float* b_src = Vb + (size_t)b_k*QSTR + b_nq;

    float acc[2][4][4] = {};
    const int nt = (row0 + 128) >> 5;

    #pragma unroll
    for (int i = 0; i < 4; i++) cp_async16(&ASM(0, a_m, a_kq + 4*i), a_src + 4*i);
    #pragma unroll
    for (int i = 0; i < 2; i++) cp_async16(&BSM(0, b_k, b_nq + 4*i), b_src + 4*i);
    CP_COMMIT();

    for (int t = 0; t < nt; t++) {
        const int cur = t & 1;
        if (t + 1 < nt) {
            const int nb = cur ^ 1;
            const int k0 = (t+1) << 5;
            #pragma unroll
            for (int i = 0; i < 4; i++)
                cp_async16(&ASM(nb, a_m, a_kq + 4*i), a_src + k0 + 4*i);
            #pragma unroll
            for (int i = 0; i < 2; i++)
                cp_async16(&BSM(nb, b_k, b_nq + 4*i), b_src + (size_t)k0*QSTR + 4*i);
            CP_COMMIT();
            CP_WAIT(1);
        } else {
            CP_WAIT(0);
        }
        __syncthreads();

        #pragma unroll
        for (int kk = 0; kk < 32; kk += 8) {
            uint32_t af[2][4];
            #pragma unroll
            for (int mt = 0; mt < 2; mt++) {
                int mb = warp_m*32 + mt*16;
                af[mt][0] = f2tf32(ASM(cur, mb+gr,   kk+ctg));
                af[mt][1] = f2tf32(ASM(cur, mb+gr+8, kk+ctg));
                af[mt][2] = f2tf32(ASM(cur, mb+gr,   kk+ctg+4));
                af[mt][3] = f2tf32(ASM(cur, mb+gr+8, kk+ctg+4));
            }
            uint32_t bf[4][2];
            #pragma unroll
            for (int ntl = 0; ntl < 4; ntl++) {
                int nb = warp_n*32 + ntl*8;
                bf[ntl][0] = __float_as_uint(BSM(cur, kk+ctg,   nb+gr));
                bf[ntl][1] = __float_as_uint(BSM(cur, kk+ctg+4, nb+gr));
            }
            #pragma unroll
            for (int mt = 0; mt < 2; mt++)
                #pragma unroll
                for (int ntl = 0; ntl < 4; ntl++)
                    MMA_TF32(acc[mt][ntl], af[mt], bf[ntl][0], bf[ntl][1]);
        }
        __syncthreads();
    }

    #pragma unroll
    for (int mt = 0; mt < 2; mt++) {
        int r = row0 + warp_m*32 + mt*16 + gr;
        #pragma unroll
        for (int ntl = 0; ntl < 4; ntl++) {
            int c = warp_n*32 + ntl*8 + 2*ctg;
            float* dst = O + (size_t)(b*SS + r)*DD + hh*DK + c;
            *(float2*)dst = make_float2(tf32r(acc[mt][ntl][0]), tf32r(acc[mt][ntl][1]));
            *(float2*)(dst + 8*DD) = make_float2(tf32r(acc[mt][ntl][2]), tf32r(acc[mt][ntl][3]));
        }
    }
#undef ASM
#undef BSM
}

// ---------------- residual add + layernorm (float4 I/O) -------------------
__global__ void add_ln_kernel(const float* __restrict__ res,
                              const float* __restrict__ x,
                              const float* __restrict__ g,
                              const float* __restrict__ be,
                              float* __restrict__ out,
                              float* __restrict__ outt)
{
    const int row = blockIdx.x;
    const int tid = threadIdx.x;
    __shared__ float buf[DD];
    __shared__ float red[256];

    float s = 0.0f;
    if (tid < DD/4) {
        float4 a = ((const float4*)(res + (size_t)row*DD))[tid];
        float4 b = ((const float4*)(x   + (size_t)row*DD))[tid];
        float4 v;
        v.x = a.x + b.x; v.y = a.y + b.y;
        v.z = a.z + b.z; v.w = a.w + b.w;
        ((float4*)buf)[tid] = v;
        s = v.x + v.y + v.z + v.w;
    }
    red[tid] = s; __syncthreads();
    for (int t = 128; t > 0; t >>= 1) {
        if (tid < t) red[tid] += red[tid+t];
        __syncthreads();
    }
    float mean = red[0] * (1.0f/DD);
    __syncthreads();

    float vs = 0.0f;
    for (int d = tid; d < DD; d += 256) {
        float dv = buf[d] - mean;
        vs += dv*dv;
    }
    red[tid] = vs; __syncthreads();
    for (int t = 128; t > 0; t >>= 1) {
        if (tid < t) red[tid] += red[tid+t];
        __syncthreads();
    }
    float rstd = rsqrtf(red[0] * (1.0f/DD) + 1e-5f);

    if (tid < DD/4) {
        float4 gv = ((const float4*)g)[tid];
        float4 bv = ((const float4*)be)[tid];
        float4 v  = ((const float4*)buf)[tid];
        float4 o;
        o.x = (v.x - mean)*rstd*gv.x + bv.x;
        o.y = (v.y - mean)*rstd*gv.y + bv.y;
        o.z = (v.z - mean)*rstd*gv.z + bv.z;
        o.w = (v.w - mean)*rstd*gv.w + bv.w;
        ((float4*)(out + (size_t)row*DD))[tid] = o;
        float4 t;
        t.x = tf32r(o.x); t.y = tf32r(o.y);
        t.z = tf32r(o.z); t.w = tf32r(o.w);
        ((float4*)(outt + (size_t)row*DD))[tid] = t;
    }
}

// ---------------------------------------------------------------------------
extern "C" void kernel_launch(void* const* d_in, const int* in_sizes, int n_in,
                              void* d_out, int out_size)
{
    (void)in_sizes; (void)n_in; (void)out_size;

    const int*   x    = (const int*)  d_in[0];
    const float* emb  = (const float*)d_in[2];
    const float* pe   = (const float*)d_in[3];
    const float* wq   = (const float*)d_in[4];
    const float* bq   = (const float*)d_in[5];
    const float* wk   = (const float*)d_in[6];
    const float* bk   = (const float*)d_in[7];
    const float* wv   = (const float*)d_in[8];
    const float* bv   = (const float*)d_in[9];
    const float* wo   = (const float*)d_in[10];
    const float* bo   = (const float*)d_in[11];
    const float* w1   = (const float*)d_in[12];
    const float* b1   = (const float*)d_in[13];
    const float* w2   = (const float*)d_in[14];
    const float* b2   = (const float*)d_in[15];
    const float* g1   = (const float*)d_in[16];
    const float* be1  = (const float*)d_in[17];
    const float* g2   = (const float*)d_in[18];
    const float* be2  = (const float*)d_in[19];
    const float* wout = (const float*)d_in[20];
    const float* bout = (const float*)d_in[21];
    float* out = (float*)d_out;

    static float *p_h=nullptr,*p_ht,*p_qkv,*p_ot,*p_p,*p_fft;
    static float *p_wqkv[LL], *p_wo[LL], *p_w1[LL], *p_w2[LL], *p_wout, *p_b3[LL];
    static cudaStream_t s2 = nullptr;
    static cudaEvent_t evFork, evQKV[LL], evWO[LL], evW12[LL], evWout;
    if (!p_h) {
        void* p;
        cudaGetSymbolAddress(&p, g_h);    p_h   = (float*)p;
        cudaGetSymbolAddress(&p, g_ht);   p_ht  = (float*)p;
        cudaGetSymbolAddress(&p, g_qkv);  p_qkv = (float*)p;
        cudaGetSymbolAddress(&p, g_ot);   p_ot  = (float*)p;
        cudaGetSymbolAddress(&p, g_p);    p_p   = (float*)p;
        cudaGetSymbolAddress(&p, g_fft);  p_fft = (float*)p;
        cudaGetSymbolAddress(&p, g_wqkv); p_wqkv[0] = (float*)p; p_wqkv[1] = p_wqkv[0] + (size_t)DD*QSTR;
        cudaGetSymbolAddress(&p, g_wo);   p_wo[0]   = (float*)p; p_wo[1]   = p_wo[0]   + (size_t)DD*DD;
        cudaGetSymbolAddress(&p, g_w1);   p_w1[0]   = (float*)p; p_w1[1]   = p_w1[0]   + (size_t)DD*DFF;
        cudaGetSymbolAddress(&p, g_w2);   p_w2[0]   = (float*)p; p_w2[1]   = p_w2[0]   + (size_t)DFF*DD;
        cudaGetSymbolAddress(&p, g_wout); p_wout = (float*)p;
        cudaGetSymbolAddress(&p, g_b3);   p_b3[0] = (float*)p; p_b3[1] = p_b3[0] + QSTR;
        cudaFuncSetAttribute(gemm_tf32_kernel,
            cudaFuncAttributeMaxDynamicSharedMemorySize, GEMM_SMEM);
        cudaFuncSetAttribute(attn_scores_gemm,
            cudaFuncAttributeMaxDynamicSharedMemorySize, SCORES_SMEM);
        cudaFuncSetAttribute(attn_o_mma_kernel,
            cudaFuncAttributeMaxDynamicSharedMemorySize, ATTN_SMEM);
        cudaStreamCreateWithFlags(&s2, cudaStreamNonBlocking);
        cudaEventCreateWithFlags(&evFork, cudaEventDisableTiming);
        cudaEventCreateWithFlags(&evWout, cudaEventDisableTiming);
        for (int l = 0; l < LL; l++) {
            cudaEventCreateWithFlags(&evQKV[l], cudaEventDisableTiming);
            cudaEventCreateWithFlags(&evWO[l],  cudaEventDisableTiming);
            cudaEventCreateWithFlags(&evW12[l], cudaEventDisableTiming);
        }
    }

    // ---- fork side stream for weight conversions ----
    cudaEventRecord(evFork, 0);
    cudaStreamWaitEvent(s2, evFork, 0);

    const int wblk  = (DD*DD/4 + 255)/256;
    const int wblk1 = ((int)((size_t)DD*DFF/4) + 255)/256;
    const int wblkO = ((int)((size_t)DD*VV/4) + 255)/256;

    for (int l = 0; l < LL; l++) {
        const float* wq_l = wq + (size_t)l*DD*DD;
        const float* wk_l = wk + (size_t)l*DD*DD;
        const float* wv_l = wv + (size_t)l*DD*DD;
        cvt_tf32_cols_kernel<<<wblk, 256, 0, s2>>>(wq_l, p_wqkv[l], DD, DD, QSTR, 0);
        cvt_tf32_cols_kernel<<<wblk, 256, 0, s2>>>(wk_l, p_wqkv[l], DD, DD, QSTR, DD);
        cvt_tf32_cols_kernel<<<wblk, 256, 0, s2>>>(wv_l, p_wqkv[l], DD, DD, QSTR, 2*DD);
        concat3_kernel<<<(QSTR+255)/256, 256, 0, s2>>>(bq + l*DD, bk + l*DD, bv + l*DD, p_b3[l]);
        cudaEventRecord(evQKV[l], s2);
        cvt_tf32_kernel<<<wblk, 256, 0, s2>>>((const float4*)(wo + (size_t)l*DD*DD),
                                              (float4*)p_wo[l], DD*DD/4);
        cudaEventRecord(evWO[l], s2);
        cvt_tf32_kernel<<<wblk1, 256, 0, s2>>>((const float4*)(w1 + (size_t)l*DD*DFF),
                                               (float4*)p_w1[l], (int)((size_t)DD*DFF/4));
        cvt_tf32_kernel<<<wblk1, 256, 0, s2>>>((const float4*)(w2 + (size_t)l*DFF*DD),
                                               (float4*)p_w2[l], (int)((size_t)DFF*DD/4));
        cudaEventRecord(evW12[l], s2);
    }
    cvt_tf32_kernel<<<wblkO, 256, 0, s2>>>((const float4*)wout, (float4*)p_wout,
                                           (int)((size_t)DD*VV/4));
    cudaEventRecord(evWout, s2);

    // ---- main stream ----
    embed_kernel<<<(MM*DD/4 + 255)/256, 256>>>(x, emb, pe);

    for (int l = 0; l < LL; l++) {
        // fused QKV
        cudaStreamWaitEvent(0, evQKV[l], 0);
        dim3 gqkv(MM/128, QSTR/256);
        gemm_tf32_kernel<<<gqkv, 512, GEMM_SMEM>>>(p_ht, p_wqkv[l], p_b3[l], p_qkv, DD, QSTR, 2);

        // attention
        float* amap_l = out + LOGITS_ELEMS + (size_t)l*AMAP_ELEMS;
        dim3 gsc(36, BB*HH);
        attn_scores_gemm<<<gsc, 256, SCORES_SMEM>>>(p_qkv, amap_l);
        dim3 gsm(SS, BB*HH);
        softmax_rows<<<gsm, 256>>>(amap_l);
        dim3 gao(SS/128, BB*HH);
        attn_o_mma_kernel<<<gao, 256, ATTN_SMEM>>>(amap_l, p_qkv, p_ot);

        // output projection
        cudaStreamWaitEvent(0, evWO[l], 0);
        dim3 gproj(MM/128, DD/256);
        gemm_tf32_kernel<<<gproj, 512, GEMM_SMEM>>>(p_ot, p_wo[l], bo + l*DD, p_p, DD, DD, 0);
        add_ln_kernel<<<MM, 256>>>(p_h, p_p, g1 + l*DD, be1 + l*DD, p_h, p_ht);

        // FFN
        cudaStreamWaitEvent(0, evW12[l], 0);
        dim3 gff1(MM/128, DFF/256);
        gemm_tf32_kernel<<<gff1, 512, GEMM_SMEM>>>(p_ht, p_w1[l], b1 + l*DFF, p_fft, DD, DFF, 3);
        dim3 gff2(MM/128, DD/256);
        gemm_tf32_kernel<<<gff2, 512, GEMM_SMEM>>>(p_fft, p_w2[l], b2 + l*DD, p_p, DFF, DD, 0);
        add_ln_kernel<<<MM, 256>>>(p_h, p_p, g2 + l*DD, be2 + l*DD, p_h, p_ht);
    }

    // logits
    cudaStreamWaitEvent(0, evWout, 0);
    dim3 glog(MM/128, VV/256);
    gemm_tf32_kernel<<<glog, 512, GEMM_SMEM>>>(p_ht, p_wout, bout, out, DD, VV, 0);
}